// round 1
// baseline (speedup 1.0000x reference)
#include <cuda_runtime.h>
#include <math.h>

// Problem dims
#define B_   8
#define KB_  16
#define SEQ_ 512
#define HID_ 768
#define NPAIR (B_ * KB_)     // 128

// Scratch (device globals -- allocation inside kernel_launch is forbidden)
__device__ float g_qn[B_ * SEQ_ * HID_];          // 12.6 MB
__device__ float g_kn[KB_ * SEQ_ * HID_];         // 25.2 MB
__device__ float g_C[(size_t)NPAIR * SEQ_ * SEQ_]; // 128 MB

// ---------------------------------------------------------------------------
// Pass A: L2 normalize rows of length 768. One 256-thread block per row.
// ---------------------------------------------------------------------------
__device__ __forceinline__ void norm_row(const float* __restrict__ x,
                                         float* __restrict__ y) {
    int t = threadIdx.x;
    float v0 = x[t], v1 = x[t + 256], v2 = x[t + 512];
    float s = v0 * v0 + v1 * v1 + v2 * v2;
    #pragma unroll
    for (int o = 16; o; o >>= 1) s += __shfl_xor_sync(0xFFFFFFFFu, s, o);
    __shared__ float ws[8];
    if ((t & 31) == 0) ws[t >> 5] = s;
    __syncthreads();
    float tot = 0.f;
    #pragma unroll
    for (int w = 0; w < 8; w++) tot += ws[w];
    float inv = 1.f / fmaxf(sqrtf(tot), 1e-12f);
    y[t] = v0 * inv; y[t + 256] = v1 * inv; y[t + 512] = v2 * inv;
}

__global__ void norm_q_kernel(const float* __restrict__ src) {
    size_t off = (size_t)blockIdx.x * HID_;
    norm_row(src + off, g_qn + off);
}
__global__ void norm_k_kernel(const float* __restrict__ src) {
    size_t off = (size_t)blockIdx.x * HID_;
    norm_row(src + off, g_kn + off);
}

// ---------------------------------------------------------------------------
// Pass B: batched NT GEMM  C[p][s][t] = qn_i[s,:] . kn_j[t,:]
// Tile 128x64, k-tile 16, 256 threads, 8x4 microtile per thread.
// ---------------------------------------------------------------------------
#define BM 128
#define BN 64
#define BK 16
#define AS_LD 132   // padded, float4-aligned (132*4 % 16 == 0)
#define BS_LD 68

__global__ __launch_bounds__(256) void gemm_kernel() {
    int pair = blockIdx.z;
    int i = pair >> 4;          // / KB_
    int j = pair & 15;
    const float* __restrict__ A = g_qn + (size_t)i * SEQ_ * HID_;
    const float* __restrict__ Bm = g_kn + (size_t)j * SEQ_ * HID_;
    float* __restrict__ Cp = g_C + (size_t)pair * SEQ_ * SEQ_;

    int m0 = blockIdx.y * BM;
    int n0 = blockIdx.x * BN;

    __shared__ float As[BK][AS_LD];
    __shared__ float Bs[BK][BS_LD];

    int tid = threadIdx.x;
    int tx = tid & 15;          // 0..15 -> n
    int ty = tid >> 4;          // 0..15 -> m

    float acc[8][4];
    #pragma unroll
    for (int a = 0; a < 8; a++)
        #pragma unroll
        for (int b = 0; b < 4; b++) acc[a][b] = 0.f;

    for (int k0 = 0; k0 < HID_; k0 += BK) {
        // Load A tile: 128 rows x 16 k  = 512 float4, 2 per thread
        #pragma unroll
        for (int l = 0; l < 2; l++) {
            int fid = tid + l * 256;
            int r = fid >> 2;
            int c4 = fid & 3;
            float4 v = *(const float4*)(A + (size_t)(m0 + r) * HID_ + k0 + c4 * 4);
            As[c4 * 4 + 0][r] = v.x;
            As[c4 * 4 + 1][r] = v.y;
            As[c4 * 4 + 2][r] = v.z;
            As[c4 * 4 + 3][r] = v.w;
        }
        // Load B tile: 64 rows x 16 k = 256 float4, 1 per thread
        {
            int r = tid >> 2;
            int c4 = tid & 3;
            float4 v = *(const float4*)(Bm + (size_t)(n0 + r) * HID_ + k0 + c4 * 4);
            Bs[c4 * 4 + 0][r] = v.x;
            Bs[c4 * 4 + 1][r] = v.y;
            Bs[c4 * 4 + 2][r] = v.z;
            Bs[c4 * 4 + 3][r] = v.w;
        }
        __syncthreads();

        #pragma unroll
        for (int kk = 0; kk < BK; kk++) {
            float4 a0 = *(const float4*)&As[kk][ty * 8];
            float4 a1 = *(const float4*)&As[kk][ty * 8 + 4];
            float4 bv = *(const float4*)&Bs[kk][tx * 4];
            float a[8] = {a0.x, a0.y, a0.z, a0.w, a1.x, a1.y, a1.z, a1.w};
            float b[4] = {bv.x, bv.y, bv.z, bv.w};
            #pragma unroll
            for (int ii = 0; ii < 8; ii++)
                #pragma unroll
                for (int jj = 0; jj < 4; jj++)
                    acc[ii][jj] = fmaf(a[ii], b[jj], acc[ii][jj]);
        }
        __syncthreads();
    }

    #pragma unroll
    for (int ii = 0; ii < 8; ii++) {
        float4 v = make_float4(acc[ii][0], acc[ii][1], acc[ii][2], acc[ii][3]);
        *(float4*)(Cp + (size_t)(m0 + ty * 8 + ii) * SEQ_ + n0 + tx * 4) = v;
    }
}

// ---------------------------------------------------------------------------
// Pass C: per-row masked weighted softmax expectation, atomic-reduce over s.
// One warp per (pair, s) row.
// ---------------------------------------------------------------------------
__global__ void zero_out_kernel(float* out) {
    if (threadIdx.x < NPAIR) out[threadIdx.x] = 0.f;
}

__global__ void score_kernel(const float* __restrict__ alpha_raw,
                             const int* __restrict__ q_mask,
                             const int* __restrict__ k_mask,
                             float* __restrict__ out) {
    int gw = (blockIdx.x * blockDim.x + threadIdx.x) >> 5;
    int lane = threadIdx.x & 31;
    if (gw >= NPAIR * SEQ_) return;
    int pair = gw >> 9;       // / SEQ_
    int s = gw & (SEQ_ - 1);
    int i = pair >> 4;
    int j = pair & 15;

    if (q_mask[i * SEQ_ + s] == 0) return;   // row contributes 0

    float ar = *alpha_raw;
    float alpha = ar > 0.f ? ar : 0.01f * ar;   // leaky_relu

    const float* __restrict__ row = g_C + (size_t)pair * SEQ_ * SEQ_ + (size_t)s * SEQ_;
    const int* __restrict__ km = k_mask + j * SEQ_;

    float c[16];
    float w[16];
    float mx = -INFINITY;
    #pragma unroll
    for (int u = 0; u < 16; u++) {
        int t = lane + u * 32;
        float cv = row[t];
        c[u] = cv;
        float lg = -INFINITY;
        if (km[t]) {
            float d = fabsf((float)(s - t));
            lg = cv * expf(-alpha * d);
        }
        w[u] = lg;
        mx = fmaxf(mx, lg);
    }
    #pragma unroll
    for (int o = 16; o; o >>= 1) mx = fmaxf(mx, __shfl_xor_sync(0xFFFFFFFFu, mx, o));
    if (mx == -INFINITY) return;   // no valid key -> nan_to_num -> 0

    float den = 0.f, num = 0.f;
    #pragma unroll
    for (int u = 0; u < 16; u++) {
        if (w[u] != -INFINITY) {
            float e = expf(w[u] - mx);
            den += e;
            num += e * c[u];
        }
    }
    #pragma unroll
    for (int o = 16; o; o >>= 1) {
        den += __shfl_xor_sync(0xFFFFFFFFu, den, o);
        num += __shfl_xor_sync(0xFFFFFFFFu, num, o);
    }
    if (lane == 0) atomicAdd(&out[pair], num / den);
}

// ---------------------------------------------------------------------------
// Launch
// ---------------------------------------------------------------------------
extern "C" void kernel_launch(void* const* d_in, const int* in_sizes, int n_in,
                              void* d_out, int out_size) {
    const float* q     = (const float*)d_in[0];   // [8,512,768]
    const float* k     = (const float*)d_in[1];   // [16,512,768]
    const float* alpha = (const float*)d_in[2];   // scalar
    const int*   qm    = (const int*)d_in[3];     // [8,512]
    const int*   km    = (const int*)d_in[4];     // [16,512]
    float* out = (float*)d_out;                   // [8,16]

    norm_q_kernel<<<B_ * SEQ_, 256>>>(q);
    norm_k_kernel<<<KB_ * SEQ_, 256>>>(k);

    dim3 ggrid(SEQ_ / BN, SEQ_ / BM, NPAIR);      // (8, 4, 128)
    gemm_kernel<<<ggrid, 256>>>();

    zero_out_kernel<<<1, 128>>>(out);

    int rows = NPAIR * SEQ_;                      // 65536 warps
    int blocks = (rows * 32) / 256;               // 8192
    score_kernel<<<blocks, 256>>>(alpha, qm, km, out);
}

// round 3
// speedup vs baseline: 2.3545x; 2.3545x over previous
#include <cuda_runtime.h>
#include <cuda_bf16.h>
#include <math.h>
#include <stdint.h>

// Problem dims
#define B_   8
#define KB_  16
#define SEQ_ 512
#define HID_ 768
#define NPAIR (B_ * KB_)     // 128

// ---------------------------------------------------------------------------
// Scratch (device globals; allocation is forbidden)
// ---------------------------------------------------------------------------
__device__ __nv_bfloat16 g_qh[B_ * SEQ_ * HID_];
__device__ __nv_bfloat16 g_ql[B_ * SEQ_ * HID_];
__device__ __nv_bfloat16 g_kh[KB_ * SEQ_ * HID_];
__device__ __nv_bfloat16 g_kl[KB_ * SEQ_ * HID_];
__device__ float g_C[(size_t)NPAIR * SEQ_ * SEQ_];   // 128 MB

// ---------------------------------------------------------------------------
// PTX helpers (plain sm_103 -- NO tcgen05, harness emits compute_103 PTX)
// ---------------------------------------------------------------------------
__device__ __forceinline__ uint32_t smem_u32(const void* p) {
    uint32_t a;
    asm("{ .reg .u64 t; cvta.to.shared.u64 t, %1; cvt.u32.u64 %0, t; }"
        : "=r"(a) : "l"(p));
    return a;
}

#define SWZ128(off) ((off) ^ (((off) >> 3) & 0x70))

#define CP_ASYNC16(sm, gp) \
    asm volatile("cp.async.cg.shared.global [%0], [%1], 16;" :: "r"(sm), "l"(gp))
#define CP_COMMIT() asm volatile("cp.async.commit_group;" ::: "memory")
#define CP_WAIT1()  asm volatile("cp.async.wait_group 1;" ::: "memory")
#define CP_WAIT0()  asm volatile("cp.async.wait_group 0;" ::: "memory")

#define LDSM_X4(r0, r1, r2, r3, addr) \
    asm volatile("ldmatrix.sync.aligned.m8n8.x4.shared.b16 {%0,%1,%2,%3}, [%4];" \
                 : "=r"(r0), "=r"(r1), "=r"(r2), "=r"(r3) : "r"(addr))

#define MMA_BF16(d, a, b0, b1) \
    asm volatile("mma.sync.aligned.m16n8k16.row.col.f32.bf16.bf16.f32 " \
                 "{%0,%1,%2,%3}, {%4,%5,%6,%7}, {%8,%9}, {%0,%1,%2,%3};" \
                 : "+f"((d)[0]), "+f"((d)[1]), "+f"((d)[2]), "+f"((d)[3]) \
                 : "r"((a)[0]), "r"((a)[1]), "r"((a)[2]), "r"((a)[3]), \
                   "r"(b0), "r"(b1))

// ---------------------------------------------------------------------------
// Pass A: L2 normalize rows + split into bf16 hi/lo. 256-thread block per row.
// ---------------------------------------------------------------------------
__device__ __forceinline__ void norm_split_row(const float* __restrict__ x,
                                               __nv_bfloat16* __restrict__ hi,
                                               __nv_bfloat16* __restrict__ lo) {
    int t = threadIdx.x;
    float v0 = x[t], v1 = x[t + 256], v2 = x[t + 512];
    float s = v0 * v0 + v1 * v1 + v2 * v2;
    #pragma unroll
    for (int o = 16; o; o >>= 1) s += __shfl_xor_sync(0xFFFFFFFFu, s, o);
    __shared__ float ws[8];
    if ((t & 31) == 0) ws[t >> 5] = s;
    __syncthreads();
    float tot = 0.f;
    #pragma unroll
    for (int w = 0; w < 8; w++) tot += ws[w];
    float inv = 1.f / fmaxf(sqrtf(tot), 1e-12f);
    #pragma unroll
    for (int u = 0; u < 3; u++) {
        float v = (u == 0 ? v0 : u == 1 ? v1 : v2) * inv;
        __nv_bfloat16 h = __float2bfloat16(v);
        __nv_bfloat16 l = __float2bfloat16(v - __bfloat162float(h));
        hi[t + u * 256] = h;
        lo[t + u * 256] = l;
    }
}

__global__ void norm_q_kernel(const float* __restrict__ src) {
    size_t off = (size_t)blockIdx.x * HID_;
    norm_split_row(src + off, g_qh + off, g_ql + off);
}
__global__ void norm_k_kernel(const float* __restrict__ src) {
    size_t off = (size_t)blockIdx.x * HID_;
    norm_split_row(src + off, g_kh + off, g_kl + off);
}

// ---------------------------------------------------------------------------
// Pass B: batched NT GEMM with mma.sync (bf16, hi/lo 3-product fp32 emulation)
// CTA: 128x128 tile, 8 warps (2x4), warp tile 64x32, BK=32, double buffered.
// SMEM row layout (128B, SW128 swizzled): [hi k0..31 (64B) | lo k0..31 (64B)]
// ---------------------------------------------------------------------------
#define BK 32
#define NKT (HID_ / BK)              // 24
#define TILE_B 16384                 // 128 rows * 128 B
#define STAGE_B (2 * TILE_B)         // A + B tiles
#define GEMM_SMEM (2 * STAGE_B + 1024)

__device__ __forceinline__ void load_tiles(uint32_t sA, uint32_t sB,
                                           const __nv_bfloat16* __restrict__ Ah,
                                           const __nv_bfloat16* __restrict__ Al,
                                           const __nv_bfloat16* __restrict__ Bh,
                                           const __nv_bfloat16* __restrict__ Bl,
                                           int k0, int tid) {
    #pragma unroll
    for (int it = 0; it < 4; it++) {
        int c = tid + it * 256;          // 0..1023
        int row = c >> 3;
        int ch = c & 7;
        const __nv_bfloat16* gA = (ch < 4 ? Ah : Al) + (size_t)row * HID_ + k0 + (ch & 3) * 8;
        const __nv_bfloat16* gB = (ch < 4 ? Bh : Bl) + (size_t)row * HID_ + k0 + (ch & 3) * 8;
        uint32_t off = SWZ128((uint32_t)(row * 128 + ch * 16));
        CP_ASYNC16(sA + off, gA);
        CP_ASYNC16(sB + off, gB);
    }
}

__global__ __launch_bounds__(256, 2) void gemm_mma_kernel() {
    extern __shared__ char dsm[];
    uint32_t dyn0 = smem_u32(dsm);
    uint32_t base = (dyn0 + 1023) & ~1023u;

    int tid = threadIdx.x;
    int wid = tid >> 5, lane = tid & 31;
    int warp_m = wid >> 2;               // 0..1  -> m offset *64
    int warp_n = wid & 3;                // 0..3  -> n offset *32

    int pair = blockIdx.z;
    int i = pair >> 4, j = pair & 15;
    int m0 = blockIdx.y * 128, n0 = blockIdx.x * 128;

    const __nv_bfloat16* Ah = g_qh + (size_t)(i * SEQ_ + m0) * HID_;
    const __nv_bfloat16* Al = g_ql + (size_t)(i * SEQ_ + m0) * HID_;
    const __nv_bfloat16* Bh = g_kh + (size_t)(j * SEQ_ + n0) * HID_;
    const __nv_bfloat16* Bl = g_kl + (size_t)(j * SEQ_ + n0) * HID_;

    float acc[4][4][4];
    #pragma unroll
    for (int a = 0; a < 4; a++)
        #pragma unroll
        for (int b = 0; b < 4; b++)
            #pragma unroll
            for (int c = 0; c < 4; c++) acc[a][b][c] = 0.f;

    load_tiles(base, base + TILE_B, Ah, Al, Bh, Bl, 0, tid);
    CP_COMMIT();

    for (int kt = 0; kt < NKT; kt++) {
        int cur = kt & 1;
        if (kt + 1 < NKT) {
            uint32_t st = base + ((kt + 1) & 1) * STAGE_B;
            load_tiles(st, st + TILE_B, Ah, Al, Bh, Bl, (kt + 1) * BK, tid);
            CP_COMMIT();
            CP_WAIT1();
        } else {
            CP_WAIT0();
        }
        __syncthreads();

        uint32_t sa = base + cur * STAGE_B;
        uint32_t sb = sa + TILE_B;

        #pragma unroll
        for (int s = 0; s < 2; s++) {
            uint32_t ah[4][4], al[4][4];
            uint32_t bh[4][2], bl[4][2];
            int kc = lane >> 4;                       // 0/1 : which 16B k-chunk
            #pragma unroll
            for (int mt = 0; mt < 4; mt++) {
                int row = warp_m * 64 + mt * 16 + (lane & 15);
                uint32_t oh = SWZ128((uint32_t)(row * 128 + (s * 2 + kc) * 16));
                uint32_t ol = SWZ128((uint32_t)(row * 128 + (4 + s * 2 + kc) * 16));
                LDSM_X4(ah[mt][0], ah[mt][1], ah[mt][2], ah[mt][3], sa + oh);
                LDSM_X4(al[mt][0], al[mt][1], al[mt][2], al[mt][3], sa + ol);
            }
            #pragma unroll
            for (int g = 0; g < 2; g++) {
                int row = warp_n * 32 + g * 16 + (lane & 15);
                uint32_t oh = SWZ128((uint32_t)(row * 128 + (s * 2 + kc) * 16));
                uint32_t ol = SWZ128((uint32_t)(row * 128 + (4 + s * 2 + kc) * 16));
                uint32_t r0, r1, r2, r3;
                LDSM_X4(r0, r1, r2, r3, sb + oh);
                bh[g * 2 + 0][0] = r0; bh[g * 2 + 0][1] = r2;
                bh[g * 2 + 1][0] = r1; bh[g * 2 + 1][1] = r3;
                LDSM_X4(r0, r1, r2, r3, sb + ol);
                bl[g * 2 + 0][0] = r0; bl[g * 2 + 0][1] = r2;
                bl[g * 2 + 1][0] = r1; bl[g * 2 + 1][1] = r3;
            }
            #pragma unroll
            for (int mt = 0; mt < 4; mt++)
                #pragma unroll
                for (int nt = 0; nt < 4; nt++) {
                    MMA_BF16(acc[mt][nt], ah[mt], bh[nt][0], bh[nt][1]);
                    MMA_BF16(acc[mt][nt], ah[mt], bl[nt][0], bl[nt][1]);
                    MMA_BF16(acc[mt][nt], al[mt], bh[nt][0], bh[nt][1]);
                }
        }
        __syncthreads();
    }

    // Epilogue: write 128x128 fp32 tile
    float* Cp = g_C + (size_t)pair * SEQ_ * SEQ_;
    #pragma unroll
    for (int mt = 0; mt < 4; mt++) {
        int r = m0 + warp_m * 64 + mt * 16 + (lane >> 2);
        #pragma unroll
        for (int nt = 0; nt < 4; nt++) {
            int c = n0 + warp_n * 32 + nt * 8 + (lane & 3) * 2;
            *(float2*)&Cp[(size_t)r * SEQ_ + c] =
                make_float2(acc[mt][nt][0], acc[mt][nt][1]);
            *(float2*)&Cp[(size_t)(r + 8) * SEQ_ + c] =
                make_float2(acc[mt][nt][2], acc[mt][nt][3]);
        }
    }
}

// ---------------------------------------------------------------------------
// Pass C: per-row masked weighted softmax expectation, atomic-reduce over s.
// ---------------------------------------------------------------------------
__global__ void zero_out_kernel(float* out) {
    if (threadIdx.x < NPAIR) out[threadIdx.x] = 0.f;
}

__global__ void score_kernel(const float* __restrict__ alpha_raw,
                             const int* __restrict__ q_mask,
                             const int* __restrict__ k_mask,
                             float* __restrict__ out) {
    int gw = (blockIdx.x * blockDim.x + threadIdx.x) >> 5;
    int lane = threadIdx.x & 31;
    if (gw >= NPAIR * SEQ_) return;
    int pair = gw >> 9;
    int s = gw & (SEQ_ - 1);
    int i = pair >> 4;
    int j = pair & 15;

    if (q_mask[i * SEQ_ + s] == 0) return;

    float ar = *alpha_raw;
    float alpha = ar > 0.f ? ar : 0.01f * ar;   // leaky_relu

    const float* __restrict__ row = g_C + (size_t)pair * SEQ_ * SEQ_ + (size_t)s * SEQ_;
    const int* __restrict__ km = k_mask + j * SEQ_;

    float c[16], w[16];
    float mx = -INFINITY;
    #pragma unroll
    for (int u = 0; u < 16; u++) {
        int t = lane + u * 32;
        float cv = row[t];
        c[u] = cv;
        float lg = -INFINITY;
        if (km[t]) {
            float d = fabsf((float)(s - t));
            lg = cv * expf(-alpha * d);
        }
        w[u] = lg;
        mx = fmaxf(mx, lg);
    }
    #pragma unroll
    for (int o = 16; o; o >>= 1) mx = fmaxf(mx, __shfl_xor_sync(0xFFFFFFFFu, mx, o));
    if (mx == -INFINITY) return;

    float den = 0.f, num = 0.f;
    #pragma unroll
    for (int u = 0; u < 16; u++) {
        if (w[u] != -INFINITY) {
            float e = expf(w[u] - mx);
            den += e;
            num += e * c[u];
        }
    }
    #pragma unroll
    for (int o = 16; o; o >>= 1) {
        den += __shfl_xor_sync(0xFFFFFFFFu, den, o);
        num += __shfl_xor_sync(0xFFFFFFFFu, num, o);
    }
    if (lane == 0) atomicAdd(&out[pair], num / den);
}

// ---------------------------------------------------------------------------
// Launch
// ---------------------------------------------------------------------------
extern "C" void kernel_launch(void* const* d_in, const int* in_sizes, int n_in,
                              void* d_out, int out_size) {
    const float* q     = (const float*)d_in[0];
    const float* k     = (const float*)d_in[1];
    const float* alpha = (const float*)d_in[2];
    const int*   qm    = (const int*)d_in[3];
    const int*   km    = (const int*)d_in[4];
    float* out = (float*)d_out;

    cudaFuncSetAttribute(gemm_mma_kernel,
                         cudaFuncAttributeMaxDynamicSharedMemorySize, GEMM_SMEM);

    norm_q_kernel<<<B_ * SEQ_, 256>>>(q);
    norm_k_kernel<<<KB_ * SEQ_, 256>>>(k);

    dim3 ggrid(SEQ_ / 128, SEQ_ / 128, NPAIR);   // (4, 4, 128)
    gemm_mma_kernel<<<ggrid, 256, GEMM_SMEM>>>();

    zero_out_kernel<<<1, 128>>>(out);

    int rows = NPAIR * SEQ_;
    int blocks = (rows * 32) / 256;
    score_kernel<<<blocks, 256>>>(alpha, qm, km, out);
}

// round 5
// speedup vs baseline: 2.4605x; 1.0450x over previous
#include <cuda_runtime.h>
#include <cuda_bf16.h>
#include <math.h>
#include <stdint.h>

#define B_   8
#define KB_  16
#define SEQ_ 512
#define HID_ 768

// ---------------------------------------------------------------------------
// Scratch (device globals; allocation is forbidden)
// ---------------------------------------------------------------------------
__device__ __nv_bfloat16 g_qh[B_ * SEQ_ * HID_];
__device__ __nv_bfloat16 g_ql[B_ * SEQ_ * HID_];
__device__ __nv_bfloat16 g_kh[KB_ * SEQ_ * HID_];
__device__ __nv_bfloat16 g_kl[KB_ * SEQ_ * HID_];

// ---------------------------------------------------------------------------
// PTX helpers (plain sm_103; NO tcgen05 -- harness emits compute_103 PTX)
// ---------------------------------------------------------------------------
__device__ __forceinline__ uint32_t smem_u32(const void* p) {
    uint32_t a;
    asm("{ .reg .u64 t; cvta.to.shared.u64 t, %1; cvt.u32.u64 %0, t; }"
        : "=r"(a) : "l"(p));
    return a;
}
#define SWZ128(off) ((off) ^ (((off) >> 3) & 0x70))
#define CP_ASYNC16(sm, gp) \
    asm volatile("cp.async.cg.shared.global [%0], [%1], 16;" :: "r"(sm), "l"(gp))
#define CP_COMMIT() asm volatile("cp.async.commit_group;" ::: "memory")
#define CP_WAIT1()  asm volatile("cp.async.wait_group 1;" ::: "memory")
#define CP_WAIT0()  asm volatile("cp.async.wait_group 0;" ::: "memory")
#define LDSM_X4(r0, r1, r2, r3, addr) \
    asm volatile("ldmatrix.sync.aligned.m8n8.x4.shared.b16 {%0,%1,%2,%3}, [%4];" \
                 : "=r"(r0), "=r"(r1), "=r"(r2), "=r"(r3) : "r"(addr))
#define MMA_BF16(d, a, b0, b1) \
    asm volatile("mma.sync.aligned.m16n8k16.row.col.f32.bf16.bf16.f32 " \
                 "{%0,%1,%2,%3}, {%4,%5,%6,%7}, {%8,%9}, {%0,%1,%2,%3};" \
                 : "+f"((d)[0]), "+f"((d)[1]), "+f"((d)[2]), "+f"((d)[3]) \
                 : "r"((a)[0]), "r"((a)[1]), "r"((a)[2]), "r"((a)[3]), \
                   "r"(b0), "r"(b1))

// ---------------------------------------------------------------------------
// Pass A: L2 normalize + bf16 hi/lo split
// ---------------------------------------------------------------------------
__device__ __forceinline__ void norm_split_row(const float* __restrict__ x,
                                               __nv_bfloat16* __restrict__ hi,
                                               __nv_bfloat16* __restrict__ lo) {
    int t = threadIdx.x;
    float v0 = x[t], v1 = x[t + 256], v2 = x[t + 512];
    float s = v0 * v0 + v1 * v1 + v2 * v2;
    #pragma unroll
    for (int o = 16; o; o >>= 1) s += __shfl_xor_sync(0xFFFFFFFFu, s, o);
    __shared__ float ws[8];
    if ((t & 31) == 0) ws[t >> 5] = s;
    __syncthreads();
    float tot = 0.f;
    #pragma unroll
    for (int w = 0; w < 8; w++) tot += ws[w];
    float inv = 1.f / fmaxf(sqrtf(tot), 1e-12f);
    #pragma unroll
    for (int u = 0; u < 3; u++) {
        float v = (u == 0 ? v0 : u == 1 ? v1 : v2) * inv;
        __nv_bfloat16 h = __float2bfloat16(v);
        __nv_bfloat16 l = __float2bfloat16(v - __bfloat162float(h));
        hi[t + u * 256] = h;
        lo[t + u * 256] = l;
    }
}
__global__ void norm_q_kernel(const float* __restrict__ src) {
    size_t off = (size_t)blockIdx.x * HID_;
    norm_split_row(src + off, g_qh + off, g_ql + off);
}
__global__ void norm_k_kernel(const float* __restrict__ src) {
    size_t off = (size_t)blockIdx.x * HID_;
    norm_split_row(src + off, g_kh + off, g_kl + off);
}

__global__ void zero_out_kernel(float* out) {
    if (threadIdx.x < B_ * KB_) out[threadIdx.x] = 0.f;
}

// ---------------------------------------------------------------------------
// Fused kernel: per (m-tile, pair): GEMM 128x256x768 (x2 n-chunks) on mma.sync
// (hi/lo 3-product fp32 emulation) + in-register softmax-expectation epilogue.
// No intermediate C in DRAM. No max subtraction needed: |logit| <= ~1.02.
// ---------------------------------------------------------------------------
#define BK 64
#define NKT (HID_ / BK)         // 12
#define NCHUNK 2
#define TOTKT (NKT * NCHUNK)    // 24
// Stage layout: A_hi 16K | A_lo 16K | B_hi 32K | B_lo 32K  = 96KB
#define ST_AH 0
#define ST_AL 16384
#define ST_BH 32768
#define ST_BL 65536
#define STAGE_B 98304
// smem map (relative to 1024-aligned base)
#define WTAB_OFF  (2 * STAGE_B)          // 1024 floats
#define KM_OFF    (WTAB_OFF + 4096)      // 512 floats
#define QM_OFF    (KM_OFF + 2048)        // 128 floats
#define SDEN_OFF  (QM_OFF + 512)         // 128*4 floats
#define SNUM_OFF  (SDEN_OFF + 2048)      // 128*4 floats
#define SPART_OFF (SNUM_OFF + 2048)      // 4 floats
#define FUSED_SMEM (SPART_OFF + 64 + 1024)

__device__ __forceinline__ void load_stage(uint32_t st,
                                           const __nv_bfloat16* __restrict__ Ah,
                                           const __nv_bfloat16* __restrict__ Al,
                                           const __nv_bfloat16* __restrict__ Bh,
                                           const __nv_bfloat16* __restrict__ Bl,
                                           int k0, int tid) {
    // A tiles: 128 rows x 128B
    #pragma unroll
    for (int it = 0; it < 4; it++) {
        int idx = tid + it * 256;              // 0..1023
        int r = idx >> 3, c8 = idx & 7;
        uint32_t off = SWZ128((uint32_t)(r * 128 + c8 * 16));
        CP_ASYNC16(st + ST_AH + off, Ah + (size_t)r * HID_ + k0 + c8 * 8);
        CP_ASYNC16(st + ST_AL + off, Al + (size_t)r * HID_ + k0 + c8 * 8);
    }
    // B tiles: 256 rows x 128B
    #pragma unroll
    for (int it = 0; it < 8; it++) {
        int idx = tid + it * 256;              // 0..2047
        int r = idx >> 3, c8 = idx & 7;
        uint32_t off = SWZ128((uint32_t)(r * 128 + c8 * 16));
        CP_ASYNC16(st + ST_BH + off, Bh + (size_t)r * HID_ + k0 + c8 * 8);
        CP_ASYNC16(st + ST_BL + off, Bl + (size_t)r * HID_ + k0 + c8 * 8);
    }
}

__global__ __launch_bounds__(256, 1) void fused_kernel(
        const float* __restrict__ alpha_raw,
        const int* __restrict__ q_mask,
        const int* __restrict__ k_mask,
        float* __restrict__ out) {
    extern __shared__ char dsm[];
    uint32_t dyn0 = smem_u32(dsm);
    uint32_t base = (dyn0 + 1023) & ~1023u;
    char* cbase = dsm + (base - dyn0);
    float* wtabf  = (float*)(cbase + WTAB_OFF);
    float* kmaskf = (float*)(cbase + KM_OFF);
    float* qmaskf = (float*)(cbase + QM_OFF);
    float* sden   = (float*)(cbase + SDEN_OFF);
    float* snum   = (float*)(cbase + SNUM_OFF);
    float* spart  = (float*)(cbase + SPART_OFF);

    int tid = threadIdx.x;
    int wid = tid >> 5, lane = tid & 31;
    int wm = wid >> 2;           // 0..1 -> m*64
    int wn = wid & 3;            // 0..3 -> n*64

    int mtile = blockIdx.x;      // 0..3
    int pidx = blockIdx.y;       // 0..127
    int j = pidx >> 3;           // key batch (grouped for L2 reuse)
    int i = pidx & 7;            // query batch
    int m0 = mtile * 128;

    const __nv_bfloat16* Ah = g_qh + (size_t)(i * SEQ_ + m0) * HID_;
    const __nv_bfloat16* Al = g_ql + (size_t)(i * SEQ_ + m0) * HID_;
    const __nv_bfloat16* Bh0 = g_kh + (size_t)(j * SEQ_) * HID_;
    const __nv_bfloat16* Bl0 = g_kl + (size_t)(j * SEQ_) * HID_;

    // prologue load ktG=0
    load_stage(base, Ah, Al, Bh0, Bl0, 0, tid);
    CP_COMMIT();

    // tables (overlap with first load)
    {
        float ar = __ldg(alpha_raw);
        float alpha = ar > 0.f ? ar : 0.01f * ar;
        #pragma unroll
        for (int u = 0; u < 4; u++) {
            int idx = tid + u * 256;
            wtabf[idx] = expf(-alpha * fabsf((float)(idx - 511)));
        }
        #pragma unroll
        for (int u = 0; u < 2; u++) {
            int t = tid + u * 256;
            kmaskf[t] = k_mask[j * SEQ_ + t] ? 1.f : 0.f;
        }
        if (tid < 128) qmaskf[tid] = q_mask[i * SEQ_ + m0 + tid] ? 1.f : 0.f;
    }

    float acc[4][8][4];
    #pragma unroll
    for (int a = 0; a < 4; a++)
        #pragma unroll
        for (int b = 0; b < 8; b++)
            #pragma unroll
            for (int c = 0; c < 4; c++) acc[a][b][c] = 0.f;
    float den[4][2], num[4][2];
    #pragma unroll
    for (int a = 0; a < 4; a++) { den[a][0] = den[a][1] = 0.f; num[a][0] = num[a][1] = 0.f; }

    for (int ktG = 0; ktG < TOTKT; ktG++) {
        if (ktG + 1 < TOTKT) {
            int nc = (ktG + 1) / NKT, kk = (ktG + 1) % NKT;
            uint32_t st = base + ((ktG + 1) & 1) * STAGE_B;
            load_stage(st, Ah, Al,
                       Bh0 + (size_t)(nc * 256) * HID_,
                       Bl0 + (size_t)(nc * 256) * HID_, kk * BK, tid);
            CP_COMMIT();
            CP_WAIT1();
        } else {
            CP_WAIT0();
        }
        __syncthreads();

        uint32_t st = base + (ktG & 1) * STAGE_B;
        int kc16 = (lane >> 4) * 16;
        int arow = wm * 64 + (lane & 15);

        #pragma unroll
        for (int s = 0; s < 4; s++) {
            uint32_t ah[4][4], al[4][4];
            #pragma unroll
            for (int mt = 0; mt < 4; mt++) {
                uint32_t off = SWZ128((uint32_t)((arow + mt * 16) * 128 + s * 32 + kc16));
                LDSM_X4(ah[mt][0], ah[mt][1], ah[mt][2], ah[mt][3], st + ST_AH + off);
                LDSM_X4(al[mt][0], al[mt][1], al[mt][2], al[mt][3], st + ST_AL + off);
            }
            #pragma unroll
            for (int h2 = 0; h2 < 2; h2++) {
                uint32_t bh[4][2], bl[4][2];
                #pragma unroll
                for (int g = 0; g < 2; g++) {
                    int brow = wn * 64 + h2 * 32 + g * 16 + (lane & 15);
                    uint32_t off = SWZ128((uint32_t)(brow * 128 + s * 32 + kc16));
                    uint32_t r0, r1, r2, r3;
                    LDSM_X4(r0, r1, r2, r3, st + ST_BH + off);
                    bh[g * 2 + 0][0] = r0; bh[g * 2 + 0][1] = r2;
                    bh[g * 2 + 1][0] = r1; bh[g * 2 + 1][1] = r3;
                    LDSM_X4(r0, r1, r2, r3, st + ST_BL + off);
                    bl[g * 2 + 0][0] = r0; bl[g * 2 + 0][1] = r2;
                    bl[g * 2 + 1][0] = r1; bl[g * 2 + 1][1] = r3;
                }
                #pragma unroll
                for (int mt = 0; mt < 4; mt++)
                    #pragma unroll
                    for (int nn = 0; nn < 4; nn++) {
                        int nt = h2 * 4 + nn;
                        MMA_BF16(acc[mt][nt], ah[mt], bh[nn][0], bh[nn][1]);
                        MMA_BF16(acc[mt][nt], ah[mt], bl[nn][0], bl[nn][1]);
                        MMA_BF16(acc[mt][nt], al[mt], bh[nn][0], bh[nn][1]);
                    }
            }
        }
        __syncthreads();

        if ((ktG + 1) % NKT == 0) {
            // epilogue for chunk nc = ktG / NKT (next chunk's first load already in flight)
            int nc = ktG / NKT;
            int sbase = m0 + wm * 64 + (lane >> 2) + 511;
            #pragma unroll
            for (int mt = 0; mt < 4; mt++)
                #pragma unroll
                for (int h = 0; h < 2; h++) {
                    int sidx = sbase + mt * 16 + h * 8;
                    float d_acc = 0.f, n_acc = 0.f;
                    #pragma unroll
                    for (int nt = 0; nt < 8; nt++) {
                        int c = nc * 256 + wn * 64 + nt * 8 + (lane & 3) * 2;
                        float a0 = acc[mt][nt][h * 2 + 0];
                        float a1 = acc[mt][nt][h * 2 + 1];
                        float e0 = __expf(a0 * wtabf[sidx - c]) * kmaskf[c];
                        float e1 = __expf(a1 * wtabf[sidx - c - 1]) * kmaskf[c + 1];
                        d_acc += e0 + e1;
                        n_acc += e0 * a0 + e1 * a1;
                    }
                    den[mt][h] += d_acc;
                    num[mt][h] += n_acc;
                }
            if (nc + 1 < NCHUNK) {
                #pragma unroll
                for (int a = 0; a < 4; a++)
                    #pragma unroll
                    for (int b = 0; b < 8; b++)
                        #pragma unroll
                        for (int c = 0; c < 4; c++) acc[a][b][c] = 0.f;
            }
        }
    }

    // Final reduction: quad (lanes sharing rows) -> across the 4 n-warps -> pair
    #pragma unroll
    for (int mt = 0; mt < 4; mt++)
        #pragma unroll
        for (int h = 0; h < 2; h++) {
            float d = den[mt][h], n = num[mt][h];
            d += __shfl_xor_sync(0xFFFFFFFFu, d, 1);
            d += __shfl_xor_sync(0xFFFFFFFFu, d, 2);
            n += __shfl_xor_sync(0xFFFFFFFFu, n, 1);
            n += __shfl_xor_sync(0xFFFFFFFFu, n, 2);
            if ((lane & 3) == 0) {
                int rl = wm * 64 + mt * 16 + h * 8 + (lane >> 2);
                sden[rl * 4 + wn] = d;
                snum[rl * 4 + wn] = n;
            }
        }
    __syncthreads();
    if (tid < 128) {
        float d = sden[tid * 4] + sden[tid * 4 + 1] + sden[tid * 4 + 2] + sden[tid * 4 + 3];
        float n = snum[tid * 4] + snum[tid * 4 + 1] + snum[tid * 4 + 2] + snum[tid * 4 + 3];
        float sc = (d > 0.f ? n / d : 0.f) * qmaskf[tid];
        #pragma unroll
        for (int o = 16; o; o >>= 1) sc += __shfl_xor_sync(0xFFFFFFFFu, sc, o);
        if ((tid & 31) == 0) spart[tid >> 5] = sc;
    }
    __syncthreads();
    if (tid == 0)
        atomicAdd(&out[i * KB_ + j], spart[0] + spart[1] + spart[2] + spart[3]);
}

// ---------------------------------------------------------------------------
// Launch  (fused kernel at launch index 3 so ncu -s5 profiles it)
// ---------------------------------------------------------------------------
extern "C" void kernel_launch(void* const* d_in, const int* in_sizes, int n_in,
                              void* d_out, int out_size) {
    const float* q     = (const float*)d_in[0];
    const float* k     = (const float*)d_in[1];
    const float* alpha = (const float*)d_in[2];
    const int*   qm    = (const int*)d_in[3];
    const int*   km    = (const int*)d_in[4];
    float* out = (float*)d_out;

    cudaFuncSetAttribute(fused_kernel,
                         cudaFuncAttributeMaxDynamicSharedMemorySize, FUSED_SMEM);

    norm_q_kernel<<<B_ * SEQ_, 256>>>(q);
    norm_k_kernel<<<KB_ * SEQ_, 256>>>(k);
    zero_out_kernel<<<1, 128>>>(out);

    dim3 grid(SEQ_ / 128, B_ * KB_);        // (4, 128)
    fused_kernel<<<grid, 256, FUSED_SMEM>>>(alpha, qm, km, out);
}

// round 6
// speedup vs baseline: 3.5750x; 1.4530x over previous
#include <cuda_runtime.h>
#include <cuda_fp16.h>
#include <math.h>
#include <stdint.h>

#define B_   8
#define KB_  16
#define SEQ_ 512
#define HID_ 768

// ---------------------------------------------------------------------------
// Scratch (device globals; allocation is forbidden)
// ---------------------------------------------------------------------------
__device__ __half g_qh[B_ * SEQ_ * HID_];
__device__ __half g_ql[B_ * SEQ_ * HID_];
__device__ __half g_kh[KB_ * SEQ_ * HID_];

// ---------------------------------------------------------------------------
// PTX helpers (plain sm_103; NO tcgen05 -- harness emits compute_103 PTX)
// ---------------------------------------------------------------------------
__device__ __forceinline__ uint32_t smem_u32(const void* p) {
    uint32_t a;
    asm("{ .reg .u64 t; cvta.to.shared.u64 t, %1; cvt.u32.u64 %0, t; }"
        : "=r"(a) : "l"(p));
    return a;
}
#define SWZ128(off) ((off) ^ (((off) >> 3) & 0x70))
#define CP_ASYNC16(sm, gp) \
    asm volatile("cp.async.cg.shared.global [%0], [%1], 16;" :: "r"(sm), "l"(gp))
#define CP_COMMIT() asm volatile("cp.async.commit_group;" ::: "memory")
#define CP_WAIT1()  asm volatile("cp.async.wait_group 1;" ::: "memory")
#define CP_WAIT0()  asm volatile("cp.async.wait_group 0;" ::: "memory")
#define LDSM_X4(r0, r1, r2, r3, addr) \
    asm volatile("ldmatrix.sync.aligned.m8n8.x4.shared.b16 {%0,%1,%2,%3}, [%4];" \
                 : "=r"(r0), "=r"(r1), "=r"(r2), "=r"(r3) : "r"(addr))
#define MMA_F16(d, a, b0, b1) \
    asm volatile("mma.sync.aligned.m16n8k16.row.col.f32.f16.f16.f32 " \
                 "{%0,%1,%2,%3}, {%4,%5,%6,%7}, {%8,%9}, {%0,%1,%2,%3};" \
                 : "+f"((d)[0]), "+f"((d)[1]), "+f"((d)[2]), "+f"((d)[3]) \
                 : "r"((a)[0]), "r"((a)[1]), "r"((a)[2]), "r"((a)[3]), \
                   "r"(b0), "r"(b1))

// ---------------------------------------------------------------------------
// Pass A: L2 normalize + fp16 split (Q: hi/lo, K: hi only)
// ---------------------------------------------------------------------------
__device__ __forceinline__ float row_inv_norm(const float* __restrict__ x,
                                              float& v0, float& v1, float& v2) {
    int t = threadIdx.x;
    v0 = x[t]; v1 = x[t + 256]; v2 = x[t + 512];
    float s = v0 * v0 + v1 * v1 + v2 * v2;
    #pragma unroll
    for (int o = 16; o; o >>= 1) s += __shfl_xor_sync(0xFFFFFFFFu, s, o);
    __shared__ float ws[8];
    if ((t & 31) == 0) ws[t >> 5] = s;
    __syncthreads();
    float tot = 0.f;
    #pragma unroll
    for (int w = 0; w < 8; w++) tot += ws[w];
    return 1.f / fmaxf(sqrtf(tot), 1e-12f);
}

__global__ void norm_q_kernel(const float* __restrict__ src) {
    size_t off = (size_t)blockIdx.x * HID_;
    float v0, v1, v2;
    float inv = row_inv_norm(src + off, v0, v1, v2);
    int t = threadIdx.x;
    #pragma unroll
    for (int u = 0; u < 3; u++) {
        float v = (u == 0 ? v0 : u == 1 ? v1 : v2) * inv;
        __half h = __float2half(v);
        __half l = __float2half(v - __half2float(h));
        g_qh[off + t + u * 256] = h;
        g_ql[off + t + u * 256] = l;
    }
}
__global__ void norm_k_kernel(const float* __restrict__ src) {
    size_t off = (size_t)blockIdx.x * HID_;
    float v0, v1, v2;
    float inv = row_inv_norm(src + off, v0, v1, v2);
    int t = threadIdx.x;
    #pragma unroll
    for (int u = 0; u < 3; u++) {
        float v = (u == 0 ? v0 : u == 1 ? v1 : v2) * inv;
        g_kh[off + t + u * 256] = __float2half(v);
    }
}

__global__ void zero_out_kernel(float* out) {
    if (threadIdx.x < B_ * KB_) out[threadIdx.x] = 0.f;
}

// ---------------------------------------------------------------------------
// Fused kernel: CTA = 128(m) x 128(n) tile; loops 4 n-chunks over N=512.
// GEMM via mma.sync f16 (2-product fp32 emulation) + in-register softmax
// expectation epilogue per chunk. 8 warps (2x4), warp tile 64x32.
// 2 CTAs/SM for tensor-pipe latency hiding.
// ---------------------------------------------------------------------------
#define BK 64
#define NKT (HID_ / BK)          // 12
#define NCHUNK 4
#define TOTKT (NKT * NCHUNK)     // 48
// Stage: A_hi 16K | A_lo 16K | B_hi 16K  = 48K
#define ST_AH 0
#define ST_AL 16384
#define ST_BH 32768
#define STAGE_B 49152
#define WTAB_OFF  (2 * STAGE_B)          // 1024 floats
#define KM_OFF    (WTAB_OFF + 4096)      // 512 floats
#define QM_OFF    (KM_OFF + 2048)        // 128 floats
#define SDEN_OFF  (QM_OFF + 512)         // 128*4 floats
#define SNUM_OFF  (SDEN_OFF + 2048)      // 128*4 floats
#define SPART_OFF (SNUM_OFF + 2048)      // 4 floats
#define FUSED_SMEM (SPART_OFF + 64 + 1024)

__device__ __forceinline__ void load_stage(uint32_t st,
                                           const __half* __restrict__ Ah,
                                           const __half* __restrict__ Al,
                                           const __half* __restrict__ Bh,
                                           int k0, int tid) {
    // A tiles: 128 rows x 128B (64 fp16)
    #pragma unroll
    for (int it = 0; it < 4; it++) {
        int idx = tid + it * 256;              // 0..1023
        int r = idx >> 3, c8 = idx & 7;
        uint32_t off = SWZ128((uint32_t)(r * 128 + c8 * 16));
        const __half* ga = Ah + (size_t)r * HID_ + k0 + c8 * 8;
        const __half* gl = Al + (size_t)r * HID_ + k0 + c8 * 8;
        CP_ASYNC16(st + ST_AH + off, ga);
        CP_ASYNC16(st + ST_AL + off, gl);
    }
    // B tile: 128 rows x 128B
    #pragma unroll
    for (int it = 0; it < 4; it++) {
        int idx = tid + it * 256;
        int r = idx >> 3, c8 = idx & 7;
        uint32_t off = SWZ128((uint32_t)(r * 128 + c8 * 16));
        CP_ASYNC16(st + ST_BH + off, Bh + (size_t)r * HID_ + k0 + c8 * 8);
    }
}

__global__ __launch_bounds__(256, 2) void fused_kernel(
        const float* __restrict__ alpha_raw,
        const int* __restrict__ q_mask,
        const int* __restrict__ k_mask,
        float* __restrict__ out) {
    extern __shared__ char dsm[];
    uint32_t dyn0 = smem_u32(dsm);
    uint32_t base = (dyn0 + 1023) & ~1023u;
    char* cbase = dsm + (base - dyn0);
    float* wtabf  = (float*)(cbase + WTAB_OFF);
    float* kmaskf = (float*)(cbase + KM_OFF);
    float* qmaskf = (float*)(cbase + QM_OFF);
    float* sden   = (float*)(cbase + SDEN_OFF);
    float* snum   = (float*)(cbase + SNUM_OFF);
    float* spart  = (float*)(cbase + SPART_OFF);

    int tid = threadIdx.x;
    int wid = tid >> 5, lane = tid & 31;
    int wm = wid >> 2;           // 0..1 -> m*64
    int wn = wid & 3;            // 0..3 -> n*32

    int mtile = blockIdx.x;      // 0..3
    int pidx = blockIdx.y;       // 0..127
    int j = pidx >> 3;           // key batch (grouped for L2 reuse)
    int i = pidx & 7;            // query batch
    int m0 = mtile * 128;

    const __half* Ah = g_qh + (size_t)(i * SEQ_ + m0) * HID_;
    const __half* Al = g_ql + (size_t)(i * SEQ_ + m0) * HID_;
    const __half* Bh0 = g_kh + (size_t)(j * SEQ_) * HID_;

    load_stage(base, Ah, Al, Bh0, 0, tid);
    CP_COMMIT();

    // tables (overlap with first load)
    {
        float ar = __ldg(alpha_raw);
        float alpha = ar > 0.f ? ar : 0.01f * ar;
        #pragma unroll
        for (int u = 0; u < 4; u++) {
            int idx = tid + u * 256;
            wtabf[idx] = expf(-alpha * fabsf((float)(idx - 511)));
        }
        #pragma unroll
        for (int u = 0; u < 2; u++) {
            int t = tid + u * 256;
            kmaskf[t] = k_mask[j * SEQ_ + t] ? 1.f : 0.f;
        }
        if (tid < 128) qmaskf[tid] = q_mask[i * SEQ_ + m0 + tid] ? 1.f : 0.f;
    }

    float acc[4][4][4];
    #pragma unroll
    for (int a = 0; a < 4; a++)
        #pragma unroll
        for (int b = 0; b < 4; b++)
            #pragma unroll
            for (int c = 0; c < 4; c++) acc[a][b][c] = 0.f;
    float den[4][2], num[4][2];
    #pragma unroll
    for (int a = 0; a < 4; a++) { den[a][0] = den[a][1] = 0.f; num[a][0] = num[a][1] = 0.f; }

    for (int ktG = 0; ktG < TOTKT; ktG++) {
        if (ktG + 1 < TOTKT) {
            int nc = (ktG + 1) / NKT, kk = (ktG + 1) % NKT;
            uint32_t st = base + ((ktG + 1) & 1) * STAGE_B;
            load_stage(st, Ah, Al, Bh0 + (size_t)(nc * 128) * HID_, kk * BK, tid);
            CP_COMMIT();
            CP_WAIT1();
        } else {
            CP_WAIT0();
        }
        __syncthreads();

        uint32_t st = base + (ktG & 1) * STAGE_B;
        int kc16 = (lane >> 4) * 16;
        int arow = wm * 64 + (lane & 15);
        int brow = wn * 32 + (lane & 15);

        #pragma unroll
        for (int s = 0; s < 4; s++) {
            uint32_t af[4][4];
            uint32_t bf[4][2];
            // B-hi frags: 32 n-cols
            #pragma unroll
            for (int g = 0; g < 2; g++) {
                uint32_t off = SWZ128((uint32_t)((brow + g * 16) * 128 + s * 32 + kc16));
                uint32_t r0, r1, r2, r3;
                LDSM_X4(r0, r1, r2, r3, st + ST_BH + off);
                bf[g * 2 + 0][0] = r0; bf[g * 2 + 0][1] = r2;
                bf[g * 2 + 1][0] = r1; bf[g * 2 + 1][1] = r3;
            }
            // A-hi frags + MMAs
            #pragma unroll
            for (int mt = 0; mt < 4; mt++) {
                uint32_t off = SWZ128((uint32_t)((arow + mt * 16) * 128 + s * 32 + kc16));
                LDSM_X4(af[mt][0], af[mt][1], af[mt][2], af[mt][3], st + ST_AH + off);
            }
            #pragma unroll
            for (int mt = 0; mt < 4; mt++)
                #pragma unroll
                for (int nt = 0; nt < 4; nt++)
                    MMA_F16(acc[mt][nt], af[mt], bf[nt][0], bf[nt][1]);
            // A-lo frags + MMAs (reuse af regs)
            #pragma unroll
            for (int mt = 0; mt < 4; mt++) {
                uint32_t off = SWZ128((uint32_t)((arow + mt * 16) * 128 + s * 32 + kc16));
                LDSM_X4(af[mt][0], af[mt][1], af[mt][2], af[mt][3], st + ST_AL + off);
            }
            #pragma unroll
            for (int mt = 0; mt < 4; mt++)
                #pragma unroll
                for (int nt = 0; nt < 4; nt++)
                    MMA_F16(acc[mt][nt], af[mt], bf[nt][0], bf[nt][1]);
        }
        __syncthreads();

        if ((ktG + 1) % NKT == 0) {
            // epilogue for n-chunk nc (next chunk's first loads already in flight)
            int nc = ktG / NKT;
            int sbase = m0 + wm * 64 + (lane >> 2) + 511;
            #pragma unroll
            for (int mt = 0; mt < 4; mt++)
                #pragma unroll
                for (int h = 0; h < 2; h++) {
                    int sidx = sbase + mt * 16 + h * 8;
                    float d_acc = 0.f, n_acc = 0.f;
                    #pragma unroll
                    for (int nt = 0; nt < 4; nt++) {
                        int c = nc * 128 + wn * 32 + nt * 8 + (lane & 3) * 2;
                        float a0 = acc[mt][nt][h * 2 + 0];
                        float a1 = acc[mt][nt][h * 2 + 1];
                        float e0 = __expf(a0 * wtabf[sidx - c]) * kmaskf[c];
                        float e1 = __expf(a1 * wtabf[sidx - c - 1]) * kmaskf[c + 1];
                        d_acc += e0 + e1;
                        n_acc += e0 * a0 + e1 * a1;
                        acc[mt][nt][h * 2 + 0] = 0.f;
                        acc[mt][nt][h * 2 + 1] = 0.f;
                    }
                    den[mt][h] += d_acc;
                    num[mt][h] += n_acc;
                }
        }
    }

    // Final reduction: quad -> 4 n-warps -> pair
    #pragma unroll
    for (int mt = 0; mt < 4; mt++)
        #pragma unroll
        for (int h = 0; h < 2; h++) {
            float d = den[mt][h], n = num[mt][h];
            d += __shfl_xor_sync(0xFFFFFFFFu, d, 1);
            d += __shfl_xor_sync(0xFFFFFFFFu, d, 2);
            n += __shfl_xor_sync(0xFFFFFFFFu, n, 1);
            n += __shfl_xor_sync(0xFFFFFFFFu, n, 2);
            if ((lane & 3) == 0) {
                int rl = wm * 64 + mt * 16 + h * 8 + (lane >> 2);
                sden[rl * 4 + wn] = d;
                snum[rl * 4 + wn] = n;
            }
        }
    __syncthreads();
    if (tid < 128) {
        float d = sden[tid * 4] + sden[tid * 4 + 1] + sden[tid * 4 + 2] + sden[tid * 4 + 3];
        float n = snum[tid * 4] + snum[tid * 4 + 1] + snum[tid * 4 + 2] + snum[tid * 4 + 3];
        float sc = (d > 0.f ? n / d : 0.f) * qmaskf[tid];
        #pragma unroll
        for (int o = 16; o; o >>= 1) sc += __shfl_xor_sync(0xFFFFFFFFu, sc, o);
        if ((tid & 31) == 0) spart[tid >> 5] = sc;
    }
    __syncthreads();
    if (tid == 0)
        atomicAdd(&out[i * KB_ + j], spart[0] + spart[1] + spart[2] + spart[3]);
}

// ---------------------------------------------------------------------------
// Launch
// ---------------------------------------------------------------------------
extern "C" void kernel_launch(void* const* d_in, const int* in_sizes, int n_in,
                              void* d_out, int out_size) {
    const float* q     = (const float*)d_in[0];
    const float* k     = (const float*)d_in[1];
    const float* alpha = (const float*)d_in[2];
    const int*   qm    = (const int*)d_in[3];
    const int*   km    = (const int*)d_in[4];
    float* out = (float*)d_out;

    cudaFuncSetAttribute(fused_kernel,
                         cudaFuncAttributeMaxDynamicSharedMemorySize, FUSED_SMEM);

    norm_q_kernel<<<B_ * SEQ_, 256>>>(q);
    norm_k_kernel<<<KB_ * SEQ_, 256>>>(k);
    zero_out_kernel<<<1, 128>>>(out);

    dim3 grid(SEQ_ / 128, B_ * KB_);        // (4, 128)
    fused_kernel<<<grid, 256, FUSED_SMEM>>>(alpha, qm, km, out);
}

// round 7
// speedup vs baseline: 4.1454x; 1.1595x over previous
#include <cuda_runtime.h>
#include <cuda_fp16.h>
#include <math.h>
#include <stdint.h>

#define B_   8
#define KB_  16
#define SEQ_ 512
#define HID_ 768
#define NPAIR (B_ * KB_)

// ---------------------------------------------------------------------------
// Scratch (device globals; allocation is forbidden)
// ---------------------------------------------------------------------------
__device__ __half g_qh[B_ * SEQ_ * HID_];
__device__ __half g_ql[B_ * SEQ_ * HID_];
__device__ __half g_kh[KB_ * SEQ_ * HID_];
__device__ float g_den[NPAIR * SEQ_];
__device__ float g_num[NPAIR * SEQ_];

// ---------------------------------------------------------------------------
// PTX helpers (plain sm_103; NO tcgen05 -- harness emits compute_103 PTX)
// ---------------------------------------------------------------------------
__device__ __forceinline__ uint32_t smem_u32(const void* p) {
    uint32_t a;
    asm("{ .reg .u64 t; cvta.to.shared.u64 t, %1; cvt.u32.u64 %0, t; }"
        : "=r"(a) : "l"(p));
    return a;
}
#define SWZ128(off) ((off) ^ (((off) >> 3) & 0x70))
#define CP_ASYNC16(sm, gp) \
    asm volatile("cp.async.cg.shared.global [%0], [%1], 16;" :: "r"(sm), "l"(gp))
#define CP_COMMIT() asm volatile("cp.async.commit_group;" ::: "memory")
#define CP_WAIT1()  asm volatile("cp.async.wait_group 1;" ::: "memory")
#define CP_WAIT0()  asm volatile("cp.async.wait_group 0;" ::: "memory")
#define LDSM_X4(r0, r1, r2, r3, addr) \
    asm volatile("ldmatrix.sync.aligned.m8n8.x4.shared.b16 {%0,%1,%2,%3}, [%4];" \
                 : "=r"(r0), "=r"(r1), "=r"(r2), "=r"(r3) : "r"(addr))
#define MMA_F16(d, a, b0, b1) \
    asm volatile("mma.sync.aligned.m16n8k16.row.col.f32.f16.f16.f32 " \
                 "{%0,%1,%2,%3}, {%4,%5,%6,%7}, {%8,%9}, {%0,%1,%2,%3};" \
                 : "+f"((d)[0]), "+f"((d)[1]), "+f"((d)[2]), "+f"((d)[3]) \
                 : "r"((a)[0]), "r"((a)[1]), "r"((a)[2]), "r"((a)[3]), \
                   "r"(b0), "r"(b1))

// ---------------------------------------------------------------------------
// Pass A: L2 normalize + fp16 split (Q: hi/lo, K: hi only)
// ---------------------------------------------------------------------------
__device__ __forceinline__ float row_inv_norm(const float* __restrict__ x,
                                              float& v0, float& v1, float& v2) {
    int t = threadIdx.x;
    v0 = x[t]; v1 = x[t + 256]; v2 = x[t + 512];
    float s = v0 * v0 + v1 * v1 + v2 * v2;
    #pragma unroll
    for (int o = 16; o; o >>= 1) s += __shfl_xor_sync(0xFFFFFFFFu, s, o);
    __shared__ float ws[8];
    if ((t & 31) == 0) ws[t >> 5] = s;
    __syncthreads();
    float tot = 0.f;
    #pragma unroll
    for (int w = 0; w < 8; w++) tot += ws[w];
    return 1.f / fmaxf(sqrtf(tot), 1e-12f);
}

__global__ void norm_q_kernel(const float* __restrict__ src) {
    size_t off = (size_t)blockIdx.x * HID_;
    float v0, v1, v2;
    float inv = row_inv_norm(src + off, v0, v1, v2);
    int t = threadIdx.x;
    #pragma unroll
    for (int u = 0; u < 3; u++) {
        float v = (u == 0 ? v0 : u == 1 ? v1 : v2) * inv;
        __half h = __float2half(v);
        __half l = __float2half(v - __half2float(h));
        g_qh[off + t + u * 256] = h;
        g_ql[off + t + u * 256] = l;
    }
}
__global__ void norm_k_kernel(const float* __restrict__ src) {
    size_t off = (size_t)blockIdx.x * HID_;
    float v0, v1, v2;
    float inv = row_inv_norm(src + off, v0, v1, v2);
    int t = threadIdx.x;
    #pragma unroll
    for (int u = 0; u < 3; u++)
        g_kh[off + t + u * 256] = __float2half((u == 0 ? v0 : u == 1 ? v1 : v2) * inv);
}

__global__ void zero_dn_kernel() {
    int idx = blockIdx.x * 256 + threadIdx.x;   // grid 256 -> 65536 threads
    g_den[idx] = 0.f;
    g_num[idx] = 0.f;
}

// ---------------------------------------------------------------------------
// Fused GEMM+softmax-partial kernel.
// Unit = (pair, mtile, nchunk): 128(m) x 128(n) x 768(k). 2048 CTAs.
// 8 warps (2x4), warp tile 64x32, BK=64, 2-stage cp.async.
// Partial den/num accumulated to g_den/g_num by atomicAdd.
// ---------------------------------------------------------------------------
#define BK 64
#define NKT (HID_ / BK)          // 12
#define ST_AH 0
#define ST_AL 16384
#define ST_BH 32768
#define STAGE_B 49152
#define WTAB_OFF  (2 * STAGE_B)          // 256 floats
#define KM_OFF    (WTAB_OFF + 1024)      // 128 floats
#define SDEN_OFF  (KM_OFF + 512)         // 512 floats
#define SNUM_OFF  (SDEN_OFF + 2048)      // 512 floats
#define FUSED_SMEM (SNUM_OFF + 2048 + 1024)

__global__ __launch_bounds__(256, 2) void fused_kernel(
        const float* __restrict__ alpha_raw,
        const int* __restrict__ k_mask) {
    extern __shared__ char dsm[];
    uint32_t dyn0 = smem_u32(dsm);
    uint32_t base = (dyn0 + 1023) & ~1023u;
    char* cbase = dsm + (base - dyn0);
    float* wtabf  = (float*)(cbase + WTAB_OFF);
    float* kmaskf = (float*)(cbase + KM_OFF);
    float* sden   = (float*)(cbase + SDEN_OFF);
    float* snum   = (float*)(cbase + SNUM_OFF);

    int tid = threadIdx.x;
    int wid = tid >> 5, lane = tid & 31;
    int wm = wid >> 2;            // 0..1 -> m*64
    int wn = wid & 3;             // 0..3 -> n*32

    int bid = blockIdx.x;         // 0..2047
    int pidx = bid >> 4;          // 0..127
    int rem = bid & 15;
    int mtile = rem >> 2, nch = rem & 3;
    int j = pidx >> 3;            // key batch
    int i = pidx & 7;             // query batch
    int m0 = mtile * 128, n0 = nch * 128;

    // global srcs (per-thread cp.async bases)
    int r0 = tid >> 3, c8 = tid & 7;
    const __half* gA  = g_qh + (size_t)(i * SEQ_ + m0 + r0) * HID_ + c8 * 8;
    const __half* gAl = g_ql + (size_t)(i * SEQ_ + m0 + r0) * HID_ + c8 * 8;
    const __half* gB  = g_kh + (size_t)(j * SEQ_ + n0 + r0) * HID_ + c8 * 8;
    // loop-invariant swizzled smem offsets for the 4 row-groups
    uint32_t so[4];
    #pragma unroll
    for (int it = 0; it < 4; it++)
        so[it] = SWZ128((uint32_t)((r0 + it * 32) * 128 + c8 * 16));

    // prologue: stage 0
    #pragma unroll
    for (int it = 0; it < 4; it++) {
        uint32_t o = so[it];
        size_t g = (size_t)it * 32 * HID_;
        CP_ASYNC16(base + ST_AH + o, gA + g);
        CP_ASYNC16(base + ST_AL + o, gAl + g);
        CP_ASYNC16(base + ST_BH + o, gB + g);
    }
    CP_COMMIT();

    // tables (overlap with first load)
    {
        float ar = __ldg(alpha_raw);
        float alpha = ar > 0.f ? ar : 0.01f * ar;
        if (tid < 256) {
            // t = (s_local - c_local) + 127 ; distance = |t - 127 + m0 - n0|
            wtabf[tid] = expf(-alpha * fabsf((float)(tid - 127 + m0 - n0)));
        }
        if (tid < 128) kmaskf[tid] = k_mask[j * SEQ_ + n0 + tid] ? 1.f : 0.f;
    }

    // fragment addressing constants
    uint32_t kc16 = (lane >> 4) << 4;
    uint32_t xmask = (uint32_t)(lane & 7) << 4;
    uint32_t xt0 = (0 * 32 + kc16) ^ xmask;
    uint32_t xt1 = (1 * 32 + kc16) ^ xmask;
    uint32_t xt2 = (2 * 32 + kc16) ^ xmask;
    uint32_t xt3 = (3 * 32 + kc16) ^ xmask;
    uint32_t arow0 = (uint32_t)(wm * 64 + (lane & 15)) * 128;   // + mt*2048
    uint32_t brow0 = (uint32_t)(wn * 32 + (lane & 15)) * 128;   // + g*2048

    float acc[4][4][4];
    #pragma unroll
    for (int a = 0; a < 4; a++)
        #pragma unroll
        for (int b = 0; b < 4; b++)
            #pragma unroll
            for (int c = 0; c < 4; c++) acc[a][b][c] = 0.f;

    for (int kt = 0; kt < NKT; kt++) {
        if (kt + 1 < NKT) {
            uint32_t st = base + ((kt + 1) & 1) * STAGE_B;
            size_t gk = (size_t)(kt + 1) * BK;
            #pragma unroll
            for (int it = 0; it < 4; it++) {
                uint32_t o = so[it];
                size_t g = gk + (size_t)it * 32 * HID_;
                CP_ASYNC16(st + ST_AH + o, gA + g);
                CP_ASYNC16(st + ST_AL + o, gAl + g);
                CP_ASYNC16(st + ST_BH + o, gB + g);
            }
            CP_COMMIT();
            CP_WAIT1();
        } else {
            CP_WAIT0();
        }
        __syncthreads();

        uint32_t st = base + (kt & 1) * STAGE_B;

        #pragma unroll
        for (int s = 0; s < 4; s++) {
            uint32_t xs = st + (s == 0 ? xt0 : s == 1 ? xt1 : s == 2 ? xt2 : xt3);
            uint32_t af[4][4];
            uint32_t bf[4][2];
            // B frags
            #pragma unroll
            for (int g = 0; g < 2; g++) {
                uint32_t r0_, r1_, r2_, r3_;
                LDSM_X4(r0_, r1_, r2_, r3_, xs + ST_BH + brow0 + g * 2048);
                bf[g * 2 + 0][0] = r0_; bf[g * 2 + 0][1] = r2_;
                bf[g * 2 + 1][0] = r1_; bf[g * 2 + 1][1] = r3_;
            }
            // A-hi frags + MMAs
            #pragma unroll
            for (int mt = 0; mt < 4; mt++)
                LDSM_X4(af[mt][0], af[mt][1], af[mt][2], af[mt][3],
                        xs + ST_AH + arow0 + mt * 2048);
            #pragma unroll
            for (int mt = 0; mt < 4; mt++)
                #pragma unroll
                for (int nt = 0; nt < 4; nt++)
                    MMA_F16(acc[mt][nt], af[mt], bf[nt][0], bf[nt][1]);
            // A-lo frags + MMAs
            #pragma unroll
            for (int mt = 0; mt < 4; mt++)
                LDSM_X4(af[mt][0], af[mt][1], af[mt][2], af[mt][3],
                        xs + ST_AL + arow0 + mt * 2048);
            #pragma unroll
            for (int mt = 0; mt < 4; mt++)
                #pragma unroll
                for (int nt = 0; nt < 4; nt++)
                    MMA_F16(acc[mt][nt], af[mt], bf[nt][0], bf[nt][1]);
        }
        __syncthreads();
    }

    // epilogue: softmax-expectation partials over this 128x128 tile
    float den[4][2], num[4][2];
    int sbase = wm * 64 + (lane >> 2) + 127;
    #pragma unroll
    for (int mt = 0; mt < 4; mt++)
        #pragma unroll
        for (int h = 0; h < 2; h++) {
            int sidx = sbase + mt * 16 + h * 8;
            float d_acc = 0.f, n_acc = 0.f;
            #pragma unroll
            for (int nt = 0; nt < 4; nt++) {
                int c = wn * 32 + nt * 8 + (lane & 3) * 2;
                float a0 = acc[mt][nt][h * 2 + 0];
                float a1 = acc[mt][nt][h * 2 + 1];
                float e0 = __expf(a0 * wtabf[sidx - c]) * kmaskf[c];
                float e1 = __expf(a1 * wtabf[sidx - c - 1]) * kmaskf[c + 1];
                d_acc += e0 + e1;
                n_acc += e0 * a0 + e1 * a1;
            }
            den[mt][h] = d_acc;
            num[mt][h] = n_acc;
        }

    // quad (lanes sharing a row) -> smem across the 4 n-warps -> atomics
    #pragma unroll
    for (int mt = 0; mt < 4; mt++)
        #pragma unroll
        for (int h = 0; h < 2; h++) {
            float d = den[mt][h], n = num[mt][h];
            d += __shfl_xor_sync(0xFFFFFFFFu, d, 1);
            d += __shfl_xor_sync(0xFFFFFFFFu, d, 2);
            n += __shfl_xor_sync(0xFFFFFFFFu, n, 1);
            n += __shfl_xor_sync(0xFFFFFFFFu, n, 2);
            if ((lane & 3) == 0) {
                int rl = wm * 64 + mt * 16 + h * 8 + (lane >> 2);
                sden[rl * 4 + wn] = d;
                snum[rl * 4 + wn] = n;
            }
        }
    __syncthreads();
    if (tid < 128) {
        float d = sden[tid * 4] + sden[tid * 4 + 1] + sden[tid * 4 + 2] + sden[tid * 4 + 3];
        float n = snum[tid * 4] + snum[tid * 4 + 1] + snum[tid * 4 + 2] + snum[tid * 4 + 3];
        atomicAdd(&g_den[pidx * SEQ_ + m0 + tid], d);
        atomicAdd(&g_num[pidx * SEQ_ + m0 + tid], n);
    }
}

// ---------------------------------------------------------------------------
// Final: scores = sum_s qmask * num/den  -> out[i,j]
// ---------------------------------------------------------------------------
__global__ void final_kernel(const int* __restrict__ q_mask,
                             float* __restrict__ out) {
    int pidx = blockIdx.x;        // 0..127
    int j = pidx >> 3, i = pidx & 7;
    int tid = threadIdx.x;
    float sum = 0.f;
    #pragma unroll
    for (int u = 0; u < 2; u++) {
        int s = tid + u * 256;
        float d = g_den[pidx * SEQ_ + s];
        float n = g_num[pidx * SEQ_ + s];
        if (q_mask[i * SEQ_ + s] && d > 0.f) sum += n / d;
    }
    #pragma unroll
    for (int o = 16; o; o >>= 1) sum += __shfl_xor_sync(0xFFFFFFFFu, sum, o);
    __shared__ float ws[8];
    if ((tid & 31) == 0) ws[tid >> 5] = sum;
    __syncthreads();
    if (tid == 0) {
        float t = 0.f;
        #pragma unroll
        for (int w = 0; w < 8; w++) t += ws[w];
        out[i * KB_ + j] = t;
    }
}

// ---------------------------------------------------------------------------
// Launch  (fused kernel at launch index 3 so ncu profiles it)
// ---------------------------------------------------------------------------
extern "C" void kernel_launch(void* const* d_in, const int* in_sizes, int n_in,
                              void* d_out, int out_size) {
    const float* q     = (const float*)d_in[0];
    const float* k     = (const float*)d_in[1];
    const float* alpha = (const float*)d_in[2];
    const int*   qm    = (const int*)d_in[3];
    const int*   km    = (const int*)d_in[4];
    float* out = (float*)d_out;

    cudaFuncSetAttribute(fused_kernel,
                         cudaFuncAttributeMaxDynamicSharedMemorySize, FUSED_SMEM);

    norm_q_kernel<<<B_ * SEQ_, 256>>>(q);
    norm_k_kernel<<<KB_ * SEQ_, 256>>>(k);
    zero_dn_kernel<<<256, 256>>>();

    fused_kernel<<<2048, 256, FUSED_SMEM>>>(alpha, km);

    final_kernel<<<NPAIR, 256>>>(qm, out);
}

// round 8
// speedup vs baseline: 7.2561x; 1.7504x over previous
#include <cuda_runtime.h>
#include <cuda_fp16.h>
#include <math.h>
#include <stdint.h>

#define B_   8
#define KB_  16
#define SEQ_ 512
#define HID_ 768
#define NPAIR (B_ * KB_)

// ---------------------------------------------------------------------------
// Scratch (device globals; allocation is forbidden)
// ---------------------------------------------------------------------------
__device__ __half g_qh[B_ * SEQ_ * HID_];
__device__ __half g_kh[KB_ * SEQ_ * HID_];
__device__ float g_den[NPAIR * SEQ_];
__device__ float g_num[NPAIR * SEQ_];

// ---------------------------------------------------------------------------
// PTX helpers (plain sm_103; NO tcgen05 -- harness emits compute_103 PTX)
// ---------------------------------------------------------------------------
__device__ __forceinline__ uint32_t smem_u32(const void* p) {
    uint32_t a;
    asm("{ .reg .u64 t; cvta.to.shared.u64 t, %1; cvt.u32.u64 %0, t; }"
        : "=r"(a) : "l"(p));
    return a;
}
#define SWZ128(off) ((off) ^ (((off) >> 3) & 0x70))
#define CP_ASYNC16(sm, gp) \
    asm volatile("cp.async.cg.shared.global [%0], [%1], 16;" :: "r"(sm), "l"(gp))
#define CP_COMMIT() asm volatile("cp.async.commit_group;" ::: "memory")
#define CP_WAIT1()  asm volatile("cp.async.wait_group 1;" ::: "memory")
#define CP_WAIT0()  asm volatile("cp.async.wait_group 0;" ::: "memory")
#define LDSM_X4(r0, r1, r2, r3, addr) \
    asm volatile("ldmatrix.sync.aligned.m8n8.x4.shared.b16 {%0,%1,%2,%3}, [%4];" \
                 : "=r"(r0), "=r"(r1), "=r"(r2), "=r"(r3) : "r"(addr))
#define MMA_F16(d, a, b0, b1) \
    asm volatile("mma.sync.aligned.m16n8k16.row.col.f32.f16.f16.f32 " \
                 "{%0,%1,%2,%3}, {%4,%5,%6,%7}, {%8,%9}, {%0,%1,%2,%3};" \
                 : "+f"((d)[0]), "+f"((d)[1]), "+f"((d)[2]), "+f"((d)[3]) \
                 : "r"((a)[0]), "r"((a)[1]), "r"((a)[2]), "r"((a)[3]), \
                   "r"(b0), "r"(b1))

// ---------------------------------------------------------------------------
// Pass A: L2 normalize -> fp16
// ---------------------------------------------------------------------------
__device__ __forceinline__ float row_inv_norm(const float* __restrict__ x,
                                              float& v0, float& v1, float& v2) {
    int t = threadIdx.x;
    v0 = x[t]; v1 = x[t + 256]; v2 = x[t + 512];
    float s = v0 * v0 + v1 * v1 + v2 * v2;
    #pragma unroll
    for (int o = 16; o; o >>= 1) s += __shfl_xor_sync(0xFFFFFFFFu, s, o);
    __shared__ float ws[8];
    if ((t & 31) == 0) ws[t >> 5] = s;
    __syncthreads();
    float tot = 0.f;
    #pragma unroll
    for (int w = 0; w < 8; w++) tot += ws[w];
    return 1.f / fmaxf(sqrtf(tot), 1e-12f);
}

__global__ void norm_q_kernel(const float* __restrict__ src) {
    size_t off = (size_t)blockIdx.x * HID_;
    float v0, v1, v2;
    float inv = row_inv_norm(src + off, v0, v1, v2);
    int t = threadIdx.x;
    #pragma unroll
    for (int u = 0; u < 3; u++)
        g_qh[off + t + u * 256] = __float2half((u == 0 ? v0 : u == 1 ? v1 : v2) * inv);
}
__global__ void norm_k_kernel(const float* __restrict__ src) {
    size_t off = (size_t)blockIdx.x * HID_;
    float v0, v1, v2;
    float inv = row_inv_norm(src + off, v0, v1, v2);
    int t = threadIdx.x;
    #pragma unroll
    for (int u = 0; u < 3; u++)
        g_kh[off + t + u * 256] = __float2half((u == 0 ? v0 : u == 1 ? v1 : v2) * inv);
}

__global__ void zero_dn_kernel() {
    int idx = blockIdx.x * 256 + threadIdx.x;   // grid 256 -> 65536 threads
    g_den[idx] = 0.f;
    g_num[idx] = 0.f;
}

// ---------------------------------------------------------------------------
// Fused GEMM+softmax-partial kernel.
// Unit = (pair, mtile, nchunk): 128(m) x 128(n) x 768(k). 2048 CTAs.
// 8 warps (2x4), warp tile 64x32, BK=64, 2-stage cp.async, pure fp16 operands.
// Partial den/num accumulated to g_den/g_num by atomicAdd.
// ---------------------------------------------------------------------------
#define BK 64
#define NKT (HID_ / BK)          // 12
#define ST_AH 0
#define ST_BH 16384
#define STAGE_B 32768
#define WTAB_OFF  (2 * STAGE_B)          // 256 floats
#define KM_OFF    (WTAB_OFF + 1024)      // 128 floats
#define SDEN_OFF  (KM_OFF + 512)         // 512 floats
#define SNUM_OFF  (SDEN_OFF + 2048)      // 512 floats
#define FUSED_SMEM (SNUM_OFF + 2048 + 1024)

__global__ __launch_bounds__(256, 2) void fused_kernel(
        const float* __restrict__ alpha_raw,
        const int* __restrict__ k_mask) {
    extern __shared__ char dsm[];
    uint32_t dyn0 = smem_u32(dsm);
    uint32_t base = (dyn0 + 1023) & ~1023u;
    char* cbase = dsm + (base - dyn0);
    float* wtabf  = (float*)(cbase + WTAB_OFF);
    float* kmaskf = (float*)(cbase + KM_OFF);
    float* sden   = (float*)(cbase + SDEN_OFF);
    float* snum   = (float*)(cbase + SNUM_OFF);

    int tid = threadIdx.x;
    int wid = tid >> 5, lane = tid & 31;
    int wm = wid >> 2;            // 0..1 -> m*64
    int wn = wid & 3;             // 0..3 -> n*32

    int bid = blockIdx.x;         // 0..2047
    int pidx = bid >> 4;          // 0..127
    int rem = bid & 15;
    int mtile = rem >> 2, nch = rem & 3;
    int j = pidx >> 3;            // key batch
    int i = pidx & 7;             // query batch
    int m0 = mtile * 128, n0 = nch * 128;

    // global srcs (per-thread cp.async bases)
    int r0 = tid >> 3, c8 = tid & 7;
    const __half* gA = g_qh + (size_t)(i * SEQ_ + m0 + r0) * HID_ + c8 * 8;
    const __half* gB = g_kh + (size_t)(j * SEQ_ + n0 + r0) * HID_ + c8 * 8;
    // loop-invariant swizzled smem offsets for the 4 row-groups
    uint32_t so[4];
    #pragma unroll
    for (int it = 0; it < 4; it++)
        so[it] = SWZ128((uint32_t)((r0 + it * 32) * 128 + c8 * 16));

    // prologue: stage 0
    #pragma unroll
    for (int it = 0; it < 4; it++) {
        size_t g = (size_t)it * 32 * HID_;
        CP_ASYNC16(base + ST_AH + so[it], gA + g);
        CP_ASYNC16(base + ST_BH + so[it], gB + g);
    }
    CP_COMMIT();

    // tables (overlap with first load)
    {
        float ar = __ldg(alpha_raw);
        float alpha = ar > 0.f ? ar : 0.01f * ar;
        if (tid < 256) {
            // wtab[t] = exp(-alpha * |t - 127 + m0 - n0|), t = s_loc - c_loc + 127
            wtabf[tid] = expf(-alpha * fabsf((float)(tid - 127 + m0 - n0)));
        }
        if (tid < 128) kmaskf[tid] = k_mask[j * SEQ_ + n0 + tid] ? 1.f : 0.f;
    }

    // fragment addressing constants
    uint32_t kc16 = (lane >> 4) << 4;
    uint32_t xmask = (uint32_t)(lane & 7) << 4;
    uint32_t xt[4];
    #pragma unroll
    for (int s = 0; s < 4; s++) xt[s] = ((uint32_t)(s * 32) + kc16) ^ xmask;
    uint32_t arow0 = (uint32_t)(wm * 64 + (lane & 15)) * 128;   // + mt*2048
    uint32_t brow0 = (uint32_t)(wn * 32 + (lane & 15)) * 128;   // + g*2048

    float acc[4][4][4];
    #pragma unroll
    for (int a = 0; a < 4; a++)
        #pragma unroll
        for (int b = 0; b < 4; b++)
            #pragma unroll
            for (int c = 0; c < 4; c++) acc[a][b][c] = 0.f;

    for (int kt = 0; kt < NKT; kt++) {
        if (kt + 1 < NKT) {
            uint32_t st = base + ((kt + 1) & 1) * STAGE_B;
            size_t gk = (size_t)(kt + 1) * BK;
            #pragma unroll
            for (int it = 0; it < 4; it++) {
                size_t g = gk + (size_t)it * 32 * HID_;
                CP_ASYNC16(st + ST_AH + so[it], gA + g);
                CP_ASYNC16(st + ST_BH + so[it], gB + g);
            }
            CP_COMMIT();
            CP_WAIT1();
        } else {
            CP_WAIT0();
        }
        __syncthreads();

        uint32_t st = base + (kt & 1) * STAGE_B;

        #pragma unroll
        for (int s = 0; s < 4; s++) {
            uint32_t xs = st + xt[s];
            uint32_t af[4][4];
            uint32_t bf[4][2];
            // B frags (32 n-cols)
            #pragma unroll
            for (int g = 0; g < 2; g++) {
                uint32_t q0, q1, q2, q3;
                LDSM_X4(q0, q1, q2, q3, xs + ST_BH + brow0 + g * 2048);
                bf[g * 2 + 0][0] = q0; bf[g * 2 + 0][1] = q2;
                bf[g * 2 + 1][0] = q1; bf[g * 2 + 1][1] = q3;
            }
            // A frags + MMAs
            #pragma unroll
            for (int mt = 0; mt < 4; mt++)
                LDSM_X4(af[mt][0], af[mt][1], af[mt][2], af[mt][3],
                        xs + ST_AH + arow0 + mt * 2048);
            #pragma unroll
            for (int mt = 0; mt < 4; mt++)
                #pragma unroll
                for (int nt = 0; nt < 4; nt++)
                    MMA_F16(acc[mt][nt], af[mt], bf[nt][0], bf[nt][1]);
        }
        __syncthreads();
    }

    // epilogue: softmax-expectation partials over this 128x128 tile
    float den[4][2], num[4][2];
    int sbase = wm * 64 + (lane >> 2) + 127;
    #pragma unroll
    for (int mt = 0; mt < 4; mt++)
        #pragma unroll
        for (int h = 0; h < 2; h++) {
            int sidx = sbase + mt * 16 + h * 8;
            float d_acc = 0.f, n_acc = 0.f;
            #pragma unroll
            for (int nt = 0; nt < 4; nt++) {
                int c = wn * 32 + nt * 8 + (lane & 3) * 2;
                float a0 = acc[mt][nt][h * 2 + 0];
                float a1 = acc[mt][nt][h * 2 + 1];
                float e0 = __expf(a0 * wtabf[sidx - c]) * kmaskf[c];
                float e1 = __expf(a1 * wtabf[sidx - c - 1]) * kmaskf[c + 1];
                d_acc += e0 + e1;
                n_acc += e0 * a0 + e1 * a1;
            }
            den[mt][h] = d_acc;
            num[mt][h] = n_acc;
        }

    // quad (lanes sharing a row) -> smem across the 4 n-warps -> atomics
    #pragma unroll
    for (int mt = 0; mt < 4; mt++)
        #pragma unroll
        for (int h = 0; h < 2; h++) {
            float d = den[mt][h], n = num[mt][h];
            d += __shfl_xor_sync(0xFFFFFFFFu, d, 1);
            d += __shfl_xor_sync(0xFFFFFFFFu, d, 2);
            n += __shfl_xor_sync(0xFFFFFFFFu, n, 1);
            n += __shfl_xor_sync(0xFFFFFFFFu, n, 2);
            if ((lane & 3) == 0) {
                int rl = wm * 64 + mt * 16 + h * 8 + (lane >> 2);
                sden[rl * 4 + wn] = d;
                snum[rl * 4 + wn] = n;
            }
        }
    __syncthreads();
    if (tid < 128) {
        float d = sden[tid * 4] + sden[tid * 4 + 1] + sden[tid * 4 + 2] + sden[tid * 4 + 3];
        float n = snum[tid * 4] + snum[tid * 4 + 1] + snum[tid * 4 + 2] + snum[tid * 4 + 3];
        atomicAdd(&g_den[pidx * SEQ_ + m0 + tid], d);
        atomicAdd(&g_num[pidx * SEQ_ + m0 + tid], n);
    }
}

// ---------------------------------------------------------------------------
// Final: scores = sum_s qmask * num/den  -> out[i,j]
// ---------------------------------------------------------------------------
__global__ void final_kernel(const int* __restrict__ q_mask,
                             float* __restrict__ out) {
    int pidx = blockIdx.x;        // 0..127
    int j = pidx >> 3, i = pidx & 7;
    int tid = threadIdx.x;
    float sum = 0.f;
    #pragma unroll
    for (int u = 0; u < 2; u++) {
        int s = tid + u * 256;
        float d = g_den[pidx * SEQ_ + s];
        float n = g_num[pidx * SEQ_ + s];
        if (q_mask[i * SEQ_ + s] && d > 0.f) sum += n / d;
    }
    #pragma unroll
    for (int o = 16; o; o >>= 1) sum += __shfl_xor_sync(0xFFFFFFFFu, sum, o);
    __shared__ float ws[8];
    if ((tid & 31) == 0) ws[tid >> 5] = sum;
    __syncthreads();
    if (tid == 0) {
        float t = 0.f;
        #pragma unroll
        for (int w = 0; w < 8; w++) t += ws[w];
        out[i * KB_ + j] = t;
    }
}

// ---------------------------------------------------------------------------
// Launch  (fused kernel at launch index 3 so ncu profiles it)
// ---------------------------------------------------------------------------
extern "C" void kernel_launch(void* const* d_in, const int* in_sizes, int n_in,
                              void* d_out, int out_size) {
    const float* q     = (const float*)d_in[0];
    const float* k     = (const float*)d_in[1];
    const float* alpha = (const float*)d_in[2];
    const int*   qm    = (const int*)d_in[3];
    const int*   km    = (const int*)d_in[4];
    float* out = (float*)d_out;

    cudaFuncSetAttribute(fused_kernel,
                         cudaFuncAttributeMaxDynamicSharedMemorySize, FUSED_SMEM);

    norm_q_kernel<<<B_ * SEQ_, 256>>>(q);
    norm_k_kernel<<<KB_ * SEQ_, 256>>>(k);
    zero_dn_kernel<<<256, 256>>>();

    fused_kernel<<<2048, 256, FUSED_SMEM>>>(alpha, km);

    final_kernel<<<NPAIR, 256>>>(qm, out);
}

// round 9
// speedup vs baseline: 7.3646x; 1.0150x over previous
#include <cuda_runtime.h>
#include <cuda_fp16.h>
#include <math.h>
#include <stdint.h>

#define B_   8
#define KB_  16
#define SEQ_ 512
#define HID_ 768
#define NPAIR (B_ * KB_)

// ---------------------------------------------------------------------------
// Scratch (device globals; allocation is forbidden)
// ---------------------------------------------------------------------------
__device__ __half g_qh[B_ * SEQ_ * HID_];
__device__ __half g_kh[KB_ * SEQ_ * HID_];
__device__ float g_den[NPAIR * SEQ_];
__device__ float g_num[NPAIR * SEQ_];

// ---------------------------------------------------------------------------
// PTX helpers (plain sm_103; NO tcgen05 -- harness emits compute_103 PTX)
// ---------------------------------------------------------------------------
__device__ __forceinline__ uint32_t smem_u32(const void* p) {
    uint32_t a;
    asm("{ .reg .u64 t; cvta.to.shared.u64 t, %1; cvt.u32.u64 %0, t; }"
        : "=r"(a) : "l"(p));
    return a;
}
#define SWZ128(off) ((off) ^ (((off) >> 3) & 0x70))
#define CP_ASYNC16(sm, gp) \
    asm volatile("cp.async.cg.shared.global [%0], [%1], 16;" :: "r"(sm), "l"(gp))
#define CP_COMMIT() asm volatile("cp.async.commit_group;" ::: "memory")
#define CP_WAIT1()  asm volatile("cp.async.wait_group 1;" ::: "memory")
#define CP_WAIT0()  asm volatile("cp.async.wait_group 0;" ::: "memory")
// ldmatrix with literal immediate offset (folds to SASS imm)
#define LDSM_X4O(r0, r1, r2, r3, addr, imm) \
    asm volatile("ldmatrix.sync.aligned.m8n8.x4.shared.b16 {%0,%1,%2,%3}, [%4+%5];" \
                 : "=r"(r0), "=r"(r1), "=r"(r2), "=r"(r3) : "r"(addr), "n"(imm))
#define MMA_F16(d, a, b0, b1) \
    asm volatile("mma.sync.aligned.m16n8k16.row.col.f32.f16.f16.f32 " \
                 "{%0,%1,%2,%3}, {%4,%5,%6,%7}, {%8,%9}, {%0,%1,%2,%3};" \
                 : "+f"((d)[0]), "+f"((d)[1]), "+f"((d)[2]), "+f"((d)[3]) \
                 : "r"((a)[0]), "r"((a)[1]), "r"((a)[2]), "r"((a)[3]), \
                   "r"(b0), "r"(b1))

// ---------------------------------------------------------------------------
// Pass A: L2 normalize -> fp16
// ---------------------------------------------------------------------------
__device__ __forceinline__ float row_inv_norm(const float* __restrict__ x,
                                              float& v0, float& v1, float& v2) {
    int t = threadIdx.x;
    v0 = x[t]; v1 = x[t + 256]; v2 = x[t + 512];
    float s = v0 * v0 + v1 * v1 + v2 * v2;
    #pragma unroll
    for (int o = 16; o; o >>= 1) s += __shfl_xor_sync(0xFFFFFFFFu, s, o);
    __shared__ float ws[8];
    if ((t & 31) == 0) ws[t >> 5] = s;
    __syncthreads();
    float tot = 0.f;
    #pragma unroll
    for (int w = 0; w < 8; w++) tot += ws[w];
    return 1.f / fmaxf(sqrtf(tot), 1e-12f);
}

__global__ void norm_q_kernel(const float* __restrict__ src) {
    size_t off = (size_t)blockIdx.x * HID_;
    float v0, v1, v2;
    float inv = row_inv_norm(src + off, v0, v1, v2);
    int t = threadIdx.x;
    #pragma unroll
    for (int u = 0; u < 3; u++)
        g_qh[off + t + u * 256] = __float2half((u == 0 ? v0 : u == 1 ? v1 : v2) * inv);
}
__global__ void norm_k_kernel(const float* __restrict__ src) {
    size_t off = (size_t)blockIdx.x * HID_;
    float v0, v1, v2;
    float inv = row_inv_norm(src + off, v0, v1, v2);
    int t = threadIdx.x;
    #pragma unroll
    for (int u = 0; u < 3; u++)
        g_kh[off + t + u * 256] = __float2half((u == 0 ? v0 : u == 1 ? v1 : v2) * inv);
}

__global__ void zero_dn_kernel() {
    int idx = blockIdx.x * 256 + threadIdx.x;
    g_den[idx] = 0.f;
    g_num[idx] = 0.f;
}

// ---------------------------------------------------------------------------
// Fused GEMM+softmax-partial kernel.
// Unit = (pair, mtile, nchunk): 128(m) x 128(n) x 768(k). 2048 CTAs.
// 8 warps (2x4), warp tile 64x32, BK=64, 3-stage cp.async ring,
// fully unrolled mainloop, one barrier per k-tile.
// ---------------------------------------------------------------------------
#define BK 64
#define NKT (HID_ / BK)          // 12
#define ST_BH 16384              // B tile offset inside a stage
#define STAGE_B 32768
#define TAB_BASE  (3 * STAGE_B)              // 98304
#define WTAB_OFF  TAB_BASE                   // 256 floats
#define KM_OFF    (TAB_BASE + 1024)          // 128 floats
#define SDEN_OFF  (TAB_BASE + 1536)          // 512 floats
#define SNUM_OFF  (TAB_BASE + 3584)          // 512 floats
#define FUSED_SMEM (TAB_BASE + 5632 + 1024)

__global__ __launch_bounds__(256, 2) void fused_kernel(
        const float* __restrict__ alpha_raw,
        const int* __restrict__ k_mask) {
    extern __shared__ char dsm[];
    uint32_t dyn0 = smem_u32(dsm);
    uint32_t base = (dyn0 + 1023) & ~1023u;
    char* cbase = dsm + (base - dyn0);
    float* wtabf  = (float*)(cbase + WTAB_OFF);
    float* kmaskf = (float*)(cbase + KM_OFF);
    float* sden   = (float*)(cbase + SDEN_OFF);
    float* snum   = (float*)(cbase + SNUM_OFF);

    int tid = threadIdx.x;
    int wid = tid >> 5, lane = tid & 31;
    int wm = wid >> 2;            // 0..1 -> m*64
    int wn = wid & 3;             // 0..3 -> n*32

    int bid = blockIdx.x;         // 0..2047
    int pidx = bid >> 4;          // 0..127
    int rem = bid & 15;
    int mtile = rem >> 2, nch = rem & 3;
    int j = pidx >> 3;            // key batch
    int i = pidx & 7;             // query batch
    int m0 = mtile * 128, n0 = nch * 128;

    // stage base registers
    uint32_t stg[3] = { base, base + STAGE_B, base + 2 * STAGE_B };

    // per-thread cp.async bases
    int r0 = tid >> 3, c8 = tid & 7;
    const char* gA = (const char*)(g_qh + (size_t)(i * SEQ_ + m0 + r0) * HID_ + c8 * 8);
    const char* gB = (const char*)(g_kh + (size_t)(j * SEQ_ + n0 + r0) * HID_ + c8 * 8);
    uint32_t so[4];
    #pragma unroll
    for (int it = 0; it < 4; it++)
        so[it] = SWZ128((uint32_t)((r0 + it * 32) * 128 + c8 * 16));

    // stage loader: all offsets compile-time after unroll
    #define LOAD_STAGE(SREG, K0) do {                                          \
        _Pragma("unroll")                                                      \
        for (int it_ = 0; it_ < 4; it_++) {                                    \
            uint32_t d_ = (SREG) + so[it_];                                    \
            CP_ASYNC16(d_,          gA + (K0) * 2 + it_ * 32 * HID_ * 2);      \
            CP_ASYNC16(d_ + ST_BH,  gB + (K0) * 2 + it_ * 32 * HID_ * 2);      \
        }                                                                      \
        CP_COMMIT();                                                           \
    } while (0)

    // prologue: stages 0 and 1
    LOAD_STAGE(stg[0], 0);
    LOAD_STAGE(stg[1], BK);

    // tables (overlap with loads)
    {
        float ar = __ldg(alpha_raw);
        float alpha = ar > 0.f ? ar : 0.01f * ar;
        // wtab[t] = exp(-alpha*|t-127+m0-n0|), t = s_loc - c_loc + 127
        wtabf[tid] = expf(-alpha * fabsf((float)(tid - 127 + m0 - n0)));
        if (tid < 128) kmaskf[tid] = k_mask[j * SEQ_ + n0 + tid] ? 1.f : 0.f;
    }

    // fragment addressing constants (loop-invariant)
    uint32_t kc16 = (lane >> 4) << 4;
    uint32_t xmask = (uint32_t)(lane & 7) << 4;
    uint32_t arow0 = (uint32_t)(wm * 64 + (lane & 15)) * 128;
    uint32_t brow0 = (uint32_t)(wn * 32 + (lane & 15)) * 128;
    uint32_t xtA[4], xtB[4];
    #pragma unroll
    for (int s = 0; s < 4; s++) {
        uint32_t x = ((uint32_t)(s * 32) + kc16) ^ xmask;
        xtA[s] = x + arow0;
        xtB[s] = x + brow0 + ST_BH;
    }

    float acc[4][4][4];
    #pragma unroll
    for (int a = 0; a < 4; a++)
        #pragma unroll
        for (int b = 0; b < 4; b++)
            #pragma unroll
            for (int c = 0; c < 4; c++) acc[a][b][c] = 0.f;

    #pragma unroll
    for (int kt = 0; kt < NKT; kt++) {
        if (kt < NKT - 1) { CP_WAIT1(); } else { CP_WAIT0(); }
        __syncthreads();

        uint32_t st = stg[kt % 3];
        #pragma unroll
        for (int s = 0; s < 4; s++) {
            uint32_t aA = st + xtA[s];
            uint32_t aB = st + xtB[s];
            uint32_t af[4][4];
            uint32_t bf[4][2];
            {
                uint32_t q0, q1, q2, q3;
                LDSM_X4O(q0, q1, q2, q3, aB, 0);
                bf[0][0] = q0; bf[0][1] = q2;
                bf[1][0] = q1; bf[1][1] = q3;
                LDSM_X4O(q0, q1, q2, q3, aB, 2048);
                bf[2][0] = q0; bf[2][1] = q2;
                bf[3][0] = q1; bf[3][1] = q3;
            }
            LDSM_X4O(af[0][0], af[0][1], af[0][2], af[0][3], aA, 0);
            LDSM_X4O(af[1][0], af[1][1], af[1][2], af[1][3], aA, 2048);
            LDSM_X4O(af[2][0], af[2][1], af[2][2], af[2][3], aA, 4096);
            LDSM_X4O(af[3][0], af[3][1], af[3][2], af[3][3], aA, 6144);
            #pragma unroll
            for (int mt = 0; mt < 4; mt++)
                #pragma unroll
                for (int nt = 0; nt < 4; nt++)
                    MMA_F16(acc[mt][nt], af[mt], bf[nt][0], bf[nt][1]);
        }

        // issue next-next stage load AFTER compute (stage (kt+2)%3 was last
        // read during iteration kt-1, all warps past this kt's barrier)
        if (kt + 2 < NKT) {
            LOAD_STAGE(stg[(kt + 2) % 3], (kt + 2) * BK);
        }
    }
    #undef LOAD_STAGE

    // epilogue: softmax-expectation partials over this 128x128 tile
    float den[4][2], num[4][2];
    int sbase = wm * 64 + (lane >> 2) + 127;
    #pragma unroll
    for (int mt = 0; mt < 4; mt++)
        #pragma unroll
        for (int h = 0; h < 2; h++) {
            int sidx = sbase + mt * 16 + h * 8;
            float d_acc = 0.f, n_acc = 0.f;
            #pragma unroll
            for (int nt = 0; nt < 4; nt++) {
                int c = wn * 32 + nt * 8 + (lane & 3) * 2;
                float a0 = acc[mt][nt][h * 2 + 0];
                float a1 = acc[mt][nt][h * 2 + 1];
                float e0 = __expf(a0 * wtabf[sidx - c]) * kmaskf[c];
                float e1 = __expf(a1 * wtabf[sidx - c - 1]) * kmaskf[c + 1];
                d_acc += e0 + e1;
                n_acc += e0 * a0 + e1 * a1;
            }
            den[mt][h] = d_acc;
            num[mt][h] = n_acc;
        }

    // quad (lanes sharing a row) -> smem across the 4 n-warps -> atomics
    #pragma unroll
    for (int mt = 0; mt < 4; mt++)
        #pragma unroll
        for (int h = 0; h < 2; h++) {
            float d = den[mt][h], n = num[mt][h];
            d += __shfl_xor_sync(0xFFFFFFFFu, d, 1);
            d += __shfl_xor_sync(0xFFFFFFFFu, d, 2);
            n += __shfl_xor_sync(0xFFFFFFFFu, n, 1);
            n += __shfl_xor_sync(0xFFFFFFFFu, n, 2);
            if ((lane & 3) == 0) {
                int rl = wm * 64 + mt * 16 + h * 8 + (lane >> 2);
                sden[rl * 4 + wn] = d;
                snum[rl * 4 + wn] = n;
            }
        }
    __syncthreads();
    if (tid < 128) {
        float d = sden[tid * 4] + sden[tid * 4 + 1] + sden[tid * 4 + 2] + sden[tid * 4 + 3];
        float n = snum[tid * 4] + snum[tid * 4 + 1] + snum[tid * 4 + 2] + snum[tid * 4 + 3];
        atomicAdd(&g_den[pidx * SEQ_ + m0 + tid], d);
        atomicAdd(&g_num[pidx * SEQ_ + m0 + tid], n);
    }
}

// ---------------------------------------------------------------------------
// Final: scores = sum_s qmask * num/den  -> out[i,j]
// ---------------------------------------------------------------------------
__global__ void final_kernel(const int* __restrict__ q_mask,
                             float* __restrict__ out) {
    int pidx = blockIdx.x;
    int j = pidx >> 3, i = pidx & 7;
    int tid = threadIdx.x;
    float sum = 0.f;
    #pragma unroll
    for (int u = 0; u < 2; u++) {
        int s = tid + u * 256;
        float d = g_den[pidx * SEQ_ + s];
        float n = g_num[pidx * SEQ_ + s];
        if (q_mask[i * SEQ_ + s] && d > 0.f) sum += n / d;
    }
    #pragma unroll
    for (int o = 16; o; o >>= 1) sum += __shfl_xor_sync(0xFFFFFFFFu, sum, o);
    __shared__ float ws[8];
    if ((tid & 31) == 0) ws[tid >> 5] = sum;
    __syncthreads();
    if (tid == 0) {
        float t = 0.f;
        #pragma unroll
        for (int w = 0; w < 8; w++) t += ws[w];
        out[i * KB_ + j] = t;
    }
}

// ---------------------------------------------------------------------------
// Launch  (fused kernel at launch index 3 so ncu profiles it)
// ---------------------------------------------------------------------------
extern "C" void kernel_launch(void* const* d_in, const int* in_sizes, int n_in,
                              void* d_out, int out_size) {
    const float* q     = (const float*)d_in[0];
    const float* k     = (const float*)d_in[1];
    const float* alpha = (const float*)d_in[2];
    const int*   qm    = (const int*)d_in[3];
    const int*   km    = (const int*)d_in[4];
    float* out = (float*)d_out;

    cudaFuncSetAttribute(fused_kernel,
                         cudaFuncAttributeMaxDynamicSharedMemorySize, FUSED_SMEM);

    norm_q_kernel<<<B_ * SEQ_, 256>>>(q);
    norm_k_kernel<<<KB_ * SEQ_, 256>>>(k);
    zero_dn_kernel<<<256, 256>>>();

    fused_kernel<<<2048, 256, FUSED_SMEM>>>(alpha, km);

    final_kernel<<<NPAIR, 256>>>(qm, out);
}

// round 10
// speedup vs baseline: 7.5673x; 1.0275x over previous
#include <cuda_runtime.h>
#include <cuda_fp16.h>
#include <math.h>
#include <stdint.h>

#define B_   8
#define KB_  16
#define SEQ_ 512
#define HID_ 768
#define NPAIR (B_ * KB_)

// ---------------------------------------------------------------------------
// Scratch (device globals; allocation is forbidden)
// ---------------------------------------------------------------------------
__device__ __half g_qh[B_ * SEQ_ * HID_];
__device__ __half g_kh[KB_ * SEQ_ * HID_];
__device__ float g_den[NPAIR * SEQ_];
__device__ float g_num[NPAIR * SEQ_];

// ---------------------------------------------------------------------------
// PTX helpers (plain sm_103; NO tcgen05 -- harness emits compute_103 PTX)
// ---------------------------------------------------------------------------
__device__ __forceinline__ uint32_t smem_u32(const void* p) {
    uint32_t a;
    asm("{ .reg .u64 t; cvta.to.shared.u64 t, %1; cvt.u32.u64 %0, t; }"
        : "=r"(a) : "l"(p));
    return a;
}
#define SWZ128(off) ((off) ^ (((off) >> 3) & 0x70))
#define CP_ASYNC16(sm, gp) \
    asm volatile("cp.async.cg.shared.global [%0], [%1], 16;" :: "r"(sm), "l"(gp))
#define CP_COMMIT() asm volatile("cp.async.commit_group;" ::: "memory")
#define CP_WAIT1()  asm volatile("cp.async.wait_group 1;" ::: "memory")
#define CP_WAIT0()  asm volatile("cp.async.wait_group 0;" ::: "memory")
#define LDSM_X4O(r0, r1, r2, r3, addr, imm) \
    asm volatile("ldmatrix.sync.aligned.m8n8.x4.shared.b16 {%0,%1,%2,%3}, [%4+%5];" \
                 : "=r"(r0), "=r"(r1), "=r"(r2), "=r"(r3) : "r"(addr), "n"(imm))
#define MMA_F16(d, a, b0, b1) \
    asm volatile("mma.sync.aligned.m16n8k16.row.col.f32.f16.f16.f32 " \
                 "{%0,%1,%2,%3}, {%4,%5,%6,%7}, {%8,%9}, {%0,%1,%2,%3};" \
                 : "+f"((d)[0]), "+f"((d)[1]), "+f"((d)[2]), "+f"((d)[3]) \
                 : "r"((a)[0]), "r"((a)[1]), "r"((a)[2]), "r"((a)[3]), \
                   "r"(b0), "r"(b1))

// ---------------------------------------------------------------------------
// Pass A: L2 normalize -> fp16
// ---------------------------------------------------------------------------
__device__ __forceinline__ float row_inv_norm(const float* __restrict__ x,
                                              float& v0, float& v1, float& v2) {
    int t = threadIdx.x;
    v0 = x[t]; v1 = x[t + 256]; v2 = x[t + 512];
    float s = v0 * v0 + v1 * v1 + v2 * v2;
    #pragma unroll
    for (int o = 16; o; o >>= 1) s += __shfl_xor_sync(0xFFFFFFFFu, s, o);
    __shared__ float ws[8];
    if ((t & 31) == 0) ws[t >> 5] = s;
    __syncthreads();
    float tot = 0.f;
    #pragma unroll
    for (int w = 0; w < 8; w++) tot += ws[w];
    return 1.f / fmaxf(sqrtf(tot), 1e-12f);
}

__global__ void norm_q_kernel(const float* __restrict__ src) {
    size_t off = (size_t)blockIdx.x * HID_;
    float v0, v1, v2;
    float inv = row_inv_norm(src + off, v0, v1, v2);
    int t = threadIdx.x;
    #pragma unroll
    for (int u = 0; u < 3; u++)
        g_qh[off + t + u * 256] = __float2half((u == 0 ? v0 : u == 1 ? v1 : v2) * inv);
}
__global__ void norm_k_kernel(const float* __restrict__ src) {
    size_t off = (size_t)blockIdx.x * HID_;
    float v0, v1, v2;
    float inv = row_inv_norm(src + off, v0, v1, v2);
    int t = threadIdx.x;
    #pragma unroll
    for (int u = 0; u < 3; u++)
        g_kh[off + t + u * 256] = __float2half((u == 0 ? v0 : u == 1 ? v1 : v2) * inv);
}

__global__ void zero_dn_kernel() {
    int idx = blockIdx.x * 256 + threadIdx.x;
    g_den[idx] = 0.f;
    g_num[idx] = 0.f;
}

// ---------------------------------------------------------------------------
// Fused GEMM+softmax-partial kernel.
// Unit = (pair, mtile, nchunk): 128(m) x 128(n) x 768(k). 2048 CTAs.
// 4 warps (2x2), warp tile 64x64, BK=64, 3-stage cp.async ring,
// fully unrolled mainloop, one barrier per k-tile.
// Crossbar per CTA-kt: 64KB LDSM + 32KB cp.async = 768 cyc < 1024 tensor cyc.
// ---------------------------------------------------------------------------
#define BK 64
#define NKT (HID_ / BK)          // 12
#define ST_BH 16384              // B tile offset inside a stage
#define STAGE_B 32768
#define TAB_BASE  (3 * STAGE_B)              // 98304
#define WTAB_OFF  TAB_BASE                   // 256 floats
#define KM_OFF    (TAB_BASE + 1024)          // 128 floats
#define SDEN_OFF  (TAB_BASE + 1536)          // 256 floats
#define SNUM_OFF  (TAB_BASE + 2560)          // 256 floats
#define FUSED_SMEM (TAB_BASE + 3584 + 1024)

__global__ __launch_bounds__(128, 2) void fused_kernel(
        const float* __restrict__ alpha_raw,
        const int* __restrict__ k_mask) {
    extern __shared__ char dsm[];
    uint32_t dyn0 = smem_u32(dsm);
    uint32_t base = (dyn0 + 1023) & ~1023u;
    char* cbase = dsm + (base - dyn0);
    float* wtabf  = (float*)(cbase + WTAB_OFF);
    float* kmaskf = (float*)(cbase + KM_OFF);
    float* sden   = (float*)(cbase + SDEN_OFF);
    float* snum   = (float*)(cbase + SNUM_OFF);

    int tid = threadIdx.x;
    int wid = tid >> 5, lane = tid & 31;
    int wm = wid >> 1;            // 0..1 -> m*64
    int wn = wid & 1;             // 0..1 -> n*64

    int bid = blockIdx.x;         // 0..2047
    int pidx = bid >> 4;          // 0..127
    int rem = bid & 15;
    int mtile = rem >> 2, nch = rem & 3;
    int j = pidx >> 3;            // key batch
    int i = pidx & 7;             // query batch
    int m0 = mtile * 128, n0 = nch * 128;

    uint32_t stg[3] = { base, base + STAGE_B, base + 2 * STAGE_B };

    // per-thread cp.async bases (128 threads cover 16 rows x 8 chunks / iter)
    int r0 = tid >> 3, c8 = tid & 7;
    const char* gA = (const char*)(g_qh + (size_t)(i * SEQ_ + m0 + r0) * HID_ + c8 * 8);
    const char* gB = (const char*)(g_kh + (size_t)(j * SEQ_ + n0 + r0) * HID_ + c8 * 8);
    uint32_t so[8];
    #pragma unroll
    for (int it = 0; it < 8; it++)
        so[it] = SWZ128((uint32_t)((r0 + it * 16) * 128 + c8 * 16));

    #define LOAD_STAGE(SREG, K0) do {                                          \
        _Pragma("unroll")                                                      \
        for (int it_ = 0; it_ < 8; it_++) {                                    \
            uint32_t d_ = (SREG) + so[it_];                                    \
            CP_ASYNC16(d_,          gA + (K0) * 2 + it_ * 16 * HID_ * 2);      \
            CP_ASYNC16(d_ + ST_BH,  gB + (K0) * 2 + it_ * 16 * HID_ * 2);      \
        }                                                                      \
        CP_COMMIT();                                                           \
    } while (0)

    // prologue: stages 0 and 1
    LOAD_STAGE(stg[0], 0);
    LOAD_STAGE(stg[1], BK);

    // tables (overlap with loads)
    {
        float ar = __ldg(alpha_raw);
        float alpha = ar > 0.f ? ar : 0.01f * ar;
        #pragma unroll
        for (int u = 0; u < 2; u++) {
            int t = tid + u * 128;
            wtabf[t] = expf(-alpha * fabsf((float)(t - 127 + m0 - n0)));
        }
        kmaskf[tid] = k_mask[j * SEQ_ + n0 + tid] ? 1.f : 0.f;
    }

    // fragment addressing constants (loop-invariant)
    uint32_t kc16 = (lane >> 4) << 4;
    uint32_t xmask = (uint32_t)(lane & 7) << 4;
    uint32_t arow0 = (uint32_t)(wm * 64 + (lane & 15)) * 128;
    uint32_t brow0 = (uint32_t)(wn * 64 + (lane & 15)) * 128;
    uint32_t xtA[4], xtB[4];
    #pragma unroll
    for (int s = 0; s < 4; s++) {
        uint32_t x = ((uint32_t)(s * 32) + kc16) ^ xmask;
        xtA[s] = x + arow0;
        xtB[s] = x + brow0 + ST_BH;
    }

    float acc[4][8][4];
    #pragma unroll
    for (int a = 0; a < 4; a++)
        #pragma unroll
        for (int b = 0; b < 8; b++)
            #pragma unroll
            for (int c = 0; c < 4; c++) acc[a][b][c] = 0.f;

    #pragma unroll
    for (int kt = 0; kt < NKT; kt++) {
        if (kt < NKT - 1) { CP_WAIT1(); } else { CP_WAIT0(); }
        __syncthreads();

        uint32_t st = stg[kt % 3];
        #pragma unroll
        for (int s = 0; s < 4; s++) {
            uint32_t aA = st + xtA[s];
            uint32_t aB = st + xtB[s];
            uint32_t af[4][4];
            uint32_t bf[8][2];
            {
                uint32_t q0, q1, q2, q3;
                LDSM_X4O(q0, q1, q2, q3, aB, 0);
                bf[0][0] = q0; bf[0][1] = q2;
                bf[1][0] = q1; bf[1][1] = q3;
                LDSM_X4O(q0, q1, q2, q3, aB, 2048);
                bf[2][0] = q0; bf[2][1] = q2;
                bf[3][0] = q1; bf[3][1] = q3;
                LDSM_X4O(q0, q1, q2, q3, aB, 4096);
                bf[4][0] = q0; bf[4][1] = q2;
                bf[5][0] = q1; bf[5][1] = q3;
                LDSM_X4O(q0, q1, q2, q3, aB, 6144);
                bf[6][0] = q0; bf[6][1] = q2;
                bf[7][0] = q1; bf[7][1] = q3;
            }
            LDSM_X4O(af[0][0], af[0][1], af[0][2], af[0][3], aA, 0);
            LDSM_X4O(af[1][0], af[1][1], af[1][2], af[1][3], aA, 2048);
            LDSM_X4O(af[2][0], af[2][1], af[2][2], af[2][3], aA, 4096);
            LDSM_X4O(af[3][0], af[3][1], af[3][2], af[3][3], aA, 6144);
            #pragma unroll
            for (int mt = 0; mt < 4; mt++)
                #pragma unroll
                for (int nt = 0; nt < 8; nt++)
                    MMA_F16(acc[mt][nt], af[mt], bf[nt][0], bf[nt][1]);
        }

        if (kt + 2 < NKT) {
            LOAD_STAGE(stg[(kt + 2) % 3], (kt + 2) * BK);
        }
    }
    #undef LOAD_STAGE

    // epilogue: softmax-expectation partials over this 128x128 tile
    float den[4][2], num[4][2];
    int sbase = wm * 64 + (lane >> 2) + 127;
    #pragma unroll
    for (int mt = 0; mt < 4; mt++)
        #pragma unroll
        for (int h = 0; h < 2; h++) {
            int sidx = sbase + mt * 16 + h * 8;
            float d_acc = 0.f, n_acc = 0.f;
            #pragma unroll
            for (int nt = 0; nt < 8; nt++) {
                int c = wn * 64 + nt * 8 + (lane & 3) * 2;
                float a0 = acc[mt][nt][h * 2 + 0];
                float a1 = acc[mt][nt][h * 2 + 1];
                float e0 = __expf(a0 * wtabf[sidx - c]) * kmaskf[c];
                float e1 = __expf(a1 * wtabf[sidx - c - 1]) * kmaskf[c + 1];
                d_acc += e0 + e1;
                n_acc += e0 * a0 + e1 * a1;
            }
            den[mt][h] = d_acc;
            num[mt][h] = n_acc;
        }

    // quad (lanes sharing a row) -> smem across the 2 n-warps -> atomics
    #pragma unroll
    for (int mt = 0; mt < 4; mt++)
        #pragma unroll
        for (int h = 0; h < 2; h++) {
            float d = den[mt][h], n = num[mt][h];
            d += __shfl_xor_sync(0xFFFFFFFFu, d, 1);
            d += __shfl_xor_sync(0xFFFFFFFFu, d, 2);
            n += __shfl_xor_sync(0xFFFFFFFFu, n, 1);
            n += __shfl_xor_sync(0xFFFFFFFFu, n, 2);
            if ((lane & 3) == 0) {
                int rl = wm * 64 + mt * 16 + h * 8 + (lane >> 2);
                sden[rl * 2 + wn] = d;
                snum[rl * 2 + wn] = n;
            }
        }
    __syncthreads();
    {
        float d = sden[tid * 2] + sden[tid * 2 + 1];
        float n = snum[tid * 2] + snum[tid * 2 + 1];
        atomicAdd(&g_den[pidx * SEQ_ + m0 + tid], d);
        atomicAdd(&g_num[pidx * SEQ_ + m0 + tid], n);
    }
}

// ---------------------------------------------------------------------------
// Final: scores = sum_s qmask * num/den  -> out[i,j]
// ---------------------------------------------------------------------------
__global__ void final_kernel(const int* __restrict__ q_mask,
                             float* __restrict__ out) {
    int pidx = blockIdx.x;
    int j = pidx >> 3, i = pidx & 7;
    int tid = threadIdx.x;
    float sum = 0.f;
    #pragma unroll
    for (int u = 0; u < 2; u++) {
        int s = tid + u * 256;
        float d = g_den[pidx * SEQ_ + s];
        float n = g_num[pidx * SEQ_ + s];
        if (q_mask[i * SEQ_ + s] && d > 0.f) sum += n / d;
    }
    #pragma unroll
    for (int o = 16; o; o >>= 1) sum += __shfl_xor_sync(0xFFFFFFFFu, sum, o);
    __shared__ float ws[8];
    if ((tid & 31) == 0) ws[tid >> 5] = sum;
    __syncthreads();
    if (tid == 0) {
        float t = 0.f;
        #pragma unroll
        for (int w = 0; w < 8; w++) t += ws[w];
        out[i * KB_ + j] = t;
    }
}

// ---------------------------------------------------------------------------
// Launch  (fused kernel at launch index 3 so ncu profiles it)
// ---------------------------------------------------------------------------
extern "C" void kernel_launch(void* const* d_in, const int* in_sizes, int n_in,
                              void* d_out, int out_size) {
    const float* q     = (const float*)d_in[0];
    const float* k     = (const float*)d_in[1];
    const float* alpha = (const float*)d_in[2];
    const int*   qm    = (const int*)d_in[3];
    const int*   km    = (const int*)d_in[4];
    float* out = (float*)d_out;

    cudaFuncSetAttribute(fused_kernel,
                         cudaFuncAttributeMaxDynamicSharedMemorySize, FUSED_SMEM);

    norm_q_kernel<<<B_ * SEQ_, 256>>>(q);
    norm_k_kernel<<<KB_ * SEQ_, 256>>>(k);
    zero_dn_kernel<<<256, 256>>>();

    fused_kernel<<<2048, 128, FUSED_SMEM>>>(alpha, km);

    final_kernel<<<NPAIR, 256>>>(qm, out);
}

// round 16
// speedup vs baseline: 7.6539x; 1.0114x over previous
#include <cuda_runtime.h>
#include <cuda_fp16.h>
#include <math.h>
#include <stdint.h>

#define B_   8
#define KB_  16
#define SEQ_ 512
#define HID_ 768
#define NPAIR (B_ * KB_)

// ---------------------------------------------------------------------------
// Scratch (device globals; allocation is forbidden)
// ---------------------------------------------------------------------------
__device__ __half g_qh[B_ * SEQ_ * HID_];
__device__ __half g_kh[KB_ * SEQ_ * HID_];
__device__ float g_den[NPAIR * SEQ_];
__device__ float g_num[NPAIR * SEQ_];

// ---------------------------------------------------------------------------
// PTX helpers (plain sm_103; NO tcgen05 -- harness emits compute_103 PTX)
// ---------------------------------------------------------------------------
__device__ __forceinline__ uint32_t smem_u32(const void* p) {
    uint32_t a;
    asm("{ .reg .u64 t; cvta.to.shared.u64 t, %1; cvt.u32.u64 %0, t; }"
        : "=r"(a) : "l"(p));
    return a;
}
#define SWZ128(off) ((off) ^ (((off) >> 3) & 0x70))
#define CP_ASYNC16(sm, gp) \
    asm volatile("cp.async.cg.shared.global [%0], [%1], 16;" :: "r"(sm), "l"(gp))
#define CP_COMMIT() asm volatile("cp.async.commit_group;" ::: "memory")
#define CP_WAIT1()  asm volatile("cp.async.wait_group 1;" ::: "memory")
#define CP_WAIT0()  asm volatile("cp.async.wait_group 0;" ::: "memory")
#define LDSM_X4O(r0, r1, r2, r3, addr, imm) \
    asm volatile("ldmatrix.sync.aligned.m8n8.x4.shared.b16 {%0,%1,%2,%3}, [%4+%5];" \
                 : "=r"(r0), "=r"(r1), "=r"(r2), "=r"(r3) : "r"(addr), "n"(imm))
#define MMA_F16(d, a, b0, b1) \
    asm volatile("mma.sync.aligned.m16n8k16.row.col.f32.f16.f16.f32 " \
                 "{%0,%1,%2,%3}, {%4,%5,%6,%7}, {%8,%9}, {%0,%1,%2,%3};" \
                 : "+f"((d)[0]), "+f"((d)[1]), "+f"((d)[2]), "+f"((d)[3]) \
                 : "r"((a)[0]), "r"((a)[1]), "r"((a)[2]), "r"((a)[3]), \
                   "r"(b0), "r"(b1))

// ---------------------------------------------------------------------------
// Prep: L2 normalize -> fp16 (Q and K) + zero g_den/g_num.  One launch.
// grid = (B_+KB_)*SEQ_ = 12288 blocks of 256.
// ---------------------------------------------------------------------------
__global__ void prep_kernel(const float* __restrict__ q,
                            const float* __restrict__ k) {
    int b = blockIdx.x;
    int t = threadIdx.x;

    // zeroing piggyback: first 512 blocks clear den/num (65536 floats each)
    if (b < 256) {
        g_den[b * 256 + t] = 0.f;
    } else if (b < 512) {
        g_num[(b - 256) * 256 + t] = 0.f;
    }

    const float* src;
    __half* dst;
    if (b < B_ * SEQ_) {
        src = q + (size_t)b * HID_;
        dst = g_qh + (size_t)b * HID_;
    } else {
        int bk = b - B_ * SEQ_;
        src = k + (size_t)bk * HID_;
        dst = g_kh + (size_t)bk * HID_;
    }

    float v0 = src[t], v1 = src[t + 256], v2 = src[t + 512];
    float s = v0 * v0 + v1 * v1 + v2 * v2;
    #pragma unroll
    for (int o = 16; o; o >>= 1) s += __shfl_xor_sync(0xFFFFFFFFu, s, o);
    __shared__ float ws[8];
    if ((t & 31) == 0) ws[t >> 5] = s;
    __syncthreads();
    float tot = 0.f;
    #pragma unroll
    for (int w = 0; w < 8; w++) tot += ws[w];
    float inv = 1.f / fmaxf(sqrtf(tot), 1e-12f);
    dst[t]       = __float2half(v0 * inv);
    dst[t + 256] = __float2half(v1 * inv);
    dst[t + 512] = __float2half(v2 * inv);
}

// ---------------------------------------------------------------------------
// Fused GEMM+softmax-partial kernel.
// Unit = (pair, mtile, nchunk): 128(m) x 128(n) x 768(k). 2048 CTAs.
// 4 warps (2x2), warp tile 64x64, BK=64, 3-stage cp.async ring, one barrier
// per k-tile, software-pipelined (double-buffered) fragment loads across s.
// ---------------------------------------------------------------------------
#define BK 64
#define NKT (HID_ / BK)          // 12
#define ST_BH 16384
#define STAGE_B 32768
#define TAB_BASE  (3 * STAGE_B)
#define WTAB_OFF  TAB_BASE                   // 256 floats
#define KM_OFF    (TAB_BASE + 1024)          // 128 floats
#define SDEN_OFF  (TAB_BASE + 1536)          // 256 floats
#define SNUM_OFF  (TAB_BASE + 2560)          // 256 floats
#define FUSED_SMEM (TAB_BASE + 3584 + 1024)

__global__ __launch_bounds__(128, 2) void fused_kernel(
        const float* __restrict__ alpha_raw,
        const int* __restrict__ k_mask) {
    extern __shared__ char dsm[];
    uint32_t dyn0 = smem_u32(dsm);
    uint32_t base = (dyn0 + 1023) & ~1023u;
    char* cbase = dsm + (base - dyn0);
    float* wtabf  = (float*)(cbase + WTAB_OFF);
    float* kmaskf = (float*)(cbase + KM_OFF);
    float* sden   = (float*)(cbase + SDEN_OFF);
    float* snum   = (float*)(cbase + SNUM_OFF);

    int tid = threadIdx.x;
    int wid = tid >> 5, lane = tid & 31;
    int wm = wid >> 1;            // 0..1 -> m*64
    int wn = wid & 1;             // 0..1 -> n*64

    int bid = blockIdx.x;         // 0..2047
    int pidx = bid >> 4;          // 0..127
    int rem = bid & 15;
    int mtile = rem >> 2, nch = rem & 3;
    int j = pidx >> 3;            // key batch
    int i = pidx & 7;             // query batch
    int m0 = mtile * 128, n0 = nch * 128;

    uint32_t stg[3] = { base, base + STAGE_B, base + 2 * STAGE_B };

    // per-thread cp.async bases (128 threads cover 16 rows x 8 chunks / iter)
    int r0 = tid >> 3, c8 = tid & 7;
    const char* gA = (const char*)(g_qh + (size_t)(i * SEQ_ + m0 + r0) * HID_ + c8 * 8);
    const char* gB = (const char*)(g_kh + (size_t)(j * SEQ_ + n0 + r0) * HID_ + c8 * 8);
    uint32_t so[8];
    #pragma unroll
    for (int it = 0; it < 8; it++)
        so[it] = SWZ128((uint32_t)((r0 + it * 16) * 128 + c8 * 16));

    #define LOAD_STAGE(SREG, K0) do {                                          \
        _Pragma("unroll")                                                      \
        for (int it_ = 0; it_ < 8; it_++) {                                    \
            uint32_t d_ = (SREG) + so[it_];                                    \
            CP_ASYNC16(d_,          gA + (K0) * 2 + it_ * 16 * HID_ * 2);      \
            CP_ASYNC16(d_ + ST_BH,  gB + (K0) * 2 + it_ * 16 * HID_ * 2);      \
        }                                                                      \
        CP_COMMIT();                                                           \
    } while (0)

    LOAD_STAGE(stg[0], 0);
    LOAD_STAGE(stg[1], BK);

    // tables (overlap with loads)
    {
        float ar = __ldg(alpha_raw);
        float alpha = ar > 0.f ? ar : 0.01f * ar;
        #pragma unroll
        for (int u = 0; u < 2; u++) {
            int t = tid + u * 128;
            wtabf[t] = expf(-alpha * fabsf((float)(t - 127 + m0 - n0)));
        }
        kmaskf[tid] = k_mask[j * SEQ_ + n0 + tid] ? 1.f : 0.f;
    }

    // fragment addressing constants (loop-invariant)
    uint32_t kc16 = (lane >> 4) << 4;
    uint32_t xmask = (uint32_t)(lane & 7) << 4;
    uint32_t arow0 = (uint32_t)(wm * 64 + (lane & 15)) * 128;
    uint32_t brow0 = (uint32_t)(wn * 64 + (lane & 15)) * 128;
    uint32_t xtA[4], xtB[4];
    #pragma unroll
    for (int s = 0; s < 4; s++) {
        uint32_t x = ((uint32_t)(s * 32) + kc16) ^ xmask;
        xtA[s] = x + arow0;
        xtB[s] = x + brow0 + ST_BH;
    }

    float acc[4][8][4];
    #pragma unroll
    for (int a = 0; a < 4; a++)
        #pragma unroll
        for (int b = 0; b < 8; b++)
            #pragma unroll
            for (int c = 0; c < 4; c++) acc[a][b][c] = 0.f;

    // double-buffered fragments
    uint32_t af[2][4][4];
    uint32_t bf[2][8][2];

    #define LOAD_FRAGS(BUF, ST, S) do {                                        \
        uint32_t aA_ = (ST) + xtA[S];                                          \
        uint32_t aB_ = (ST) + xtB[S];                                          \
        uint32_t q0_, q1_, q2_, q3_;                                           \
        LDSM_X4O(q0_, q1_, q2_, q3_, aB_, 0);                                  \
        bf[BUF][0][0] = q0_; bf[BUF][0][1] = q2_;                              \
        bf[BUF][1][0] = q1_; bf[BUF][1][1] = q3_;                              \
        LDSM_X4O(q0_, q1_, q2_, q3_, aB_, 2048);                               \
        bf[BUF][2][0] = q0_; bf[BUF][2][1] = q2_;                              \
        bf[BUF][3][0] = q1_; bf[BUF][3][1] = q3_;                              \
        LDSM_X4O(q0_, q1_, q2_, q3_, aB_, 4096);                               \
        bf[BUF][4][0] = q0_; bf[BUF][4][1] = q2_;                              \
        bf[BUF][5][0] = q1_; bf[BUF][5][1] = q3_;                              \
        LDSM_X4O(q0_, q1_, q2_, q3_, aB_, 6144);                               \
        bf[BUF][6][0] = q0_; bf[BUF][6][1] = q2_;                              \
        bf[BUF][7][0] = q1_; bf[BUF][7][1] = q3_;                              \
        LDSM_X4O(af[BUF][0][0], af[BUF][0][1], af[BUF][0][2], af[BUF][0][3], aA_, 0);    \
        LDSM_X4O(af[BUF][1][0], af[BUF][1][1], af[BUF][1][2], af[BUF][1][3], aA_, 2048); \
        LDSM_X4O(af[BUF][2][0], af[BUF][2][1], af[BUF][2][2], af[BUF][2][3], aA_, 4096); \
        LDSM_X4O(af[BUF][3][0], af[BUF][3][1], af[BUF][3][2], af[BUF][3][3], aA_, 6144); \
    } while (0)

    #define DO_MMAS(BUF) do {                                                  \
        _Pragma("unroll")                                                      \
        for (int mt_ = 0; mt_ < 4; mt_++)                                      \
            _Pragma("unroll")                                                  \
            for (int nt_ = 0; nt_ < 8; nt_++)                                  \
                MMA_F16(acc[mt_][nt_], af[BUF][mt_],                           \
                        bf[BUF][nt_][0], bf[BUF][nt_][1]);                     \
    } while (0)

    #pragma unroll
    for (int kt = 0; kt < NKT; kt++) {
        if (kt < NKT - 1) { CP_WAIT1(); } else { CP_WAIT0(); }
        __syncthreads();

        uint32_t st = stg[kt % 3];
        LOAD_FRAGS(0, st, 0);
        LOAD_FRAGS(1, st, 1);
        DO_MMAS(0);
        LOAD_FRAGS(0, st, 2);
        DO_MMAS(1);
        LOAD_FRAGS(1, st, 3);
        DO_MMAS(0);
        // overlap the next-next stage load with the final MMA batch
        if (kt + 2 < NKT) {
            LOAD_STAGE(stg[(kt + 2) % 3], (kt + 2) * BK);
        }
        DO_MMAS(1);
    }
    #undef LOAD_STAGE
    #undef LOAD_FRAGS
    #undef DO_MMAS

    // epilogue: softmax-expectation partials over this 128x128 tile
    float den[4][2], num[4][2];
    int sbase = wm * 64 + (lane >> 2) + 127;
    #pragma unroll
    for (int mt = 0; mt < 4; mt++)
        #pragma unroll
        for (int h = 0; h < 2; h++) {
            int sidx = sbase + mt * 16 + h * 8;
            float d_acc = 0.f, n_acc = 0.f;
            #pragma unroll
            for (int nt = 0; nt < 8; nt++) {
                int c = wn * 64 + nt * 8 + (lane & 3) * 2;
                float a0 = acc[mt][nt][h * 2 + 0];
                float a1 = acc[mt][nt][h * 2 + 1];
                float e0 = __expf(a0 * wtabf[sidx - c]) * kmaskf[c];
                float e1 = __expf(a1 * wtabf[sidx - c - 1]) * kmaskf[c + 1];
                d_acc += e0 + e1;
                n_acc += e0 * a0 + e1 * a1;
            }
            den[mt][h] = d_acc;
            num[mt][h] = n_acc;
        }

    // quad -> smem across the 2 n-warps -> atomics
    #pragma unroll
    for (int mt = 0; mt < 4; mt++)
        #pragma unroll
        for (int h = 0; h < 2; h++) {
            float d = den[mt][h], n = num[mt][h];
            d += __shfl_xor_sync(0xFFFFFFFFu, d, 1);
            d += __shfl_xor_sync(0xFFFFFFFFu, d, 2);
            n += __shfl_xor_sync(0xFFFFFFFFu, n, 1);
            n += __shfl_xor_sync(0xFFFFFFFFu, n, 2);
            if ((lane & 3) == 0) {
                int rl = wm * 64 + mt * 16 + h * 8 + (lane >> 2);
                sden[rl * 2 + wn] = d;
                snum[rl * 2 + wn] = n;
            }
        }
    __syncthreads();
    {
        float d = sden[tid * 2] + sden[tid * 2 + 1];
        float n = snum[tid * 2] + snum[tid * 2 + 1];
        atomicAdd(&g_den[pidx * SEQ_ + m0 + tid], d);
        atomicAdd(&g_num[pidx * SEQ_ + m0 + tid], n);
    }
}

// ---------------------------------------------------------------------------
// Final: scores = sum_s qmask * num/den  -> out[i,j]
// ---------------------------------------------------------------------------
__global__ void final_kernel(const int* __restrict__ q_mask,
                             float* __restrict__ out) {
    int pidx = blockIdx.x;
    int j = pidx >> 3, i = pidx & 7;
    int tid = threadIdx.x;
    float sum = 0.f;
    #pragma unroll
    for (int u = 0; u < 2; u++) {
        int s = tid + u * 256;
        float d = g_den[pidx * SEQ_ + s];
        float n = g_num[pidx * SEQ_ + s];
        if (q_mask[i * SEQ_ + s] && d > 0.f) sum += n / d;
    }
    #pragma unroll
    for (int o = 16; o; o >>= 1) sum += __shfl_xor_sync(0xFFFFFFFFu, sum, o);
    __shared__ float ws[8];
    if ((tid & 31) == 0) ws[tid >> 5] = sum;
    __syncthreads();
    if (tid == 0) {
        float t = 0.f;
        #pragma unroll
        for (int w = 0; w < 8; w++) t += ws[w];
        out[i * KB_ + j] = t;
    }
}

// ---------------------------------------------------------------------------
// Launch
// ---------------------------------------------------------------------------
extern "C" void kernel_launch(void* const* d_in, const int* in_sizes, int n_in,
                              void* d_out, int out_size) {
    const float* q     = (const float*)d_in[0];
    const float* k     = (const float*)d_in[1];
    const float* alpha = (const float*)d_in[2];
    const int*   qm    = (const int*)d_in[3];
    const int*   km    = (const int*)d_in[4];
    float* out = (float*)d_out;

    cudaFuncSetAttribute(fused_kernel,
                         cudaFuncAttributeMaxDynamicSharedMemorySize, FUSED_SMEM);

    prep_kernel<<<(B_ + KB_) * SEQ_, 256>>>(q, k);
    fused_kernel<<<2048, 128, FUSED_SMEM>>>(alpha, km);
    final_kernel<<<NPAIR, 256>>>(qm, out);
}